// round 14
// baseline (speedup 1.0000x reference)
#include <cuda_runtime.h>
#include <cuda_bf16.h>
#include <cstdint>
#include <math.h>

#define BB 2
#define NQ 1024
#define NKV 2048
#define DM 1024
#define NH 16
#define DH 64
#define SCALE 0.125f
#define LNEPS 1e-5f

// ================= scratch (alloc-free rule: __device__ globals) ================
__device__ __nv_bfloat16 g_qnh[BB * NQ * DM], g_qnl[BB * NQ * DM];
__device__ __nv_bfloat16 g_kvnh[BB * NKV * DM], g_kvnl[BB * NKV * DM];
__device__ __nv_bfloat16 g_Wqh[DM * DM], g_Wql[DM * DM];
__device__ __nv_bfloat16 g_Wkh[DM * DM], g_Wkl[DM * DM];
__device__ __nv_bfloat16 g_Wvh[DM * DM], g_Wvl[DM * DM];
__device__ __nv_bfloat16 g_Woh[DM * DM], g_Wol[DM * DM];
__device__ __nv_bfloat16 g_ctxh[BB * NQ * NH * DH], g_ctxl[BB * NQ * NH * DH];
__device__ __nv_bfloat16 g_Qh[BB * NQ * DM], g_Ql[BB * NQ * DM];
__device__ __nv_bfloat16 g_Kh[BB * NKV * DM], g_Kl[BB * NKV * DM];
__device__ __nv_bfloat16 g_Vth[BB * NH * DH * NKV], g_Vtl[BB * NH * DH * NKV]; // [bh][d][kv]
__device__ float g_V[BB * NKV * NH * DH];
__device__ float g_mask[BB * NKV];
__device__ float g_attn_fallback[(size_t)BB * NH * NQ * NKV];

__device__ __forceinline__ void split_bf16(float x, __nv_bfloat16& h, __nv_bfloat16& l) {
    h = __float2bfloat16_rn(x);
    l = __float2bfloat16_rn(x - __bfloat162float(h));
}
__device__ __forceinline__ uint32_t smem_u32(const void* p) {
    uint32_t a;
    asm("{ .reg .u64 t; cvta.to.shared.u64 t, %1; cvt.u32.u64 %0, t; }" : "=r"(a) : "l"(p));
    return a;
}
__device__ __forceinline__ void ldsm4(uint32_t* d, uint32_t addr) {
    asm volatile("ldmatrix.sync.aligned.m8n8.x4.shared.b16 {%0,%1,%2,%3}, [%4];"
                 : "=r"(d[0]), "=r"(d[1]), "=r"(d[2]), "=r"(d[3]) : "r"(addr));
}
__device__ __forceinline__ void mma16816(float* c, const uint32_t* a, uint32_t b0, uint32_t b1) {
    asm volatile("mma.sync.aligned.m16n8k16.row.col.f32.bf16.bf16.f32 "
                 "{%0,%1,%2,%3}, {%4,%5,%6,%7}, {%8,%9}, {%0,%1,%2,%3};"
                 : "+f"(c[0]), "+f"(c[1]), "+f"(c[2]), "+f"(c[3])
                 : "r"(a[0]), "r"(a[1]), "r"(a[2]), "r"(a[3]), "r"(b0), "r"(b1));
}

// ---------------- mask normalization: dtype-agnostic ------
__global__ void mask_kernel(const unsigned char* __restrict__ m) {
    __shared__ int s_ge2, s_off;
    int t = threadIdx.x;
    if (t == 0) { s_ge2 = 0; s_off = 0; }
    __syncthreads();
    int ge2 = 0, off = 0;
    for (int i = t; i < BB * NKV; i += 256) {
        unsigned char b = m[i];
        if (b >= 2) ge2 = 1;
        if ((i & 3) && b) off = 1;
    }
    if (ge2) atomicOr(&s_ge2, 1);
    if (off) atomicOr(&s_off, 1);
    __syncthreads();
    int kind = s_ge2 ? 2 : (s_off ? 0 : 1);
    for (int i = t; i < BB * NKV; i += 256) {
        float v;
        if (kind == 2)      v = (((const float*)m)[i] != 0.0f) ? 1.0f : 0.0f;
        else if (kind == 1) v = (((const int*)m)[i] != 0) ? 1.0f : 0.0f;
        else                v = (m[i] != 0) ? 1.0f : 0.0f;
        g_mask[i] = v;
    }
}

// ---------------- LayerNorm -> bf16 hi/lo ----------------
__global__ void ln_kernel(const float* __restrict__ q, const float* __restrict__ kv,
                          const float* __restrict__ gam, const float* __restrict__ bet) {
    __shared__ float red[256];
    int row = blockIdx.x;
    const float* src;
    __nv_bfloat16 *dh, *dl;
    if (row < BB * NQ) {
        src = q + (size_t)row * DM;
        dh = g_qnh + (size_t)row * DM; dl = g_qnl + (size_t)row * DM;
    } else {
        int r = row - BB * NQ;
        src = kv + (size_t)r * DM;
        dh = g_kvnh + (size_t)r * DM; dl = g_kvnl + (size_t)r * DM;
    }
    int t = threadIdx.x;
    float4 x = ((const float4*)src)[t];
    red[t] = x.x + x.y + x.z + x.w;
    __syncthreads();
    for (int o = 128; o > 0; o >>= 1) { if (t < o) red[t] += red[t + o]; __syncthreads(); }
    float mu = red[0] * (1.0f / DM);
    __syncthreads();
    float dx = x.x - mu, dy = x.y - mu, dz = x.z - mu, dw = x.w - mu;
    red[t] = dx * dx + dy * dy + dz * dz + dw * dw;
    __syncthreads();
    for (int o = 128; o > 0; o >>= 1) { if (t < o) red[t] += red[t + o]; __syncthreads(); }
    float rstd = rsqrtf(red[0] * (1.0f / DM) + LNEPS);
    float4 g4 = ((const float4*)gam)[t];
    float4 b4 = ((const float4*)bet)[t];
    float o0 = dx * rstd * g4.x + b4.x;
    float o1 = dy * rstd * g4.y + b4.y;
    float o2 = dz * rstd * g4.z + b4.z;
    float o3 = dw * rstd * g4.w + b4.w;
    __nv_bfloat16 h[4], l[4];
    split_bf16(o0, h[0], l[0]); split_bf16(o1, h[1], l[1]);
    split_bf16(o2, h[2], l[2]); split_bf16(o3, h[3], l[3]);
    *(uint2*)(dh + 4 * t) = *(uint2*)h;
    *(uint2*)(dl + 4 * t) = *(uint2*)l;
}

// ---------------- weight transpose + bf16 split ----------------
__global__ void wconv_kernel(const float* __restrict__ W,
                             __nv_bfloat16* __restrict__ Th, __nv_bfloat16* __restrict__ Tl) {
    __shared__ float tile[32][33];
    int bx = blockIdx.x * 32;  // n
    int by = blockIdx.y * 32;  // k
    int tx = threadIdx.x, ty = threadIdx.y;
#pragma unroll
    for (int i = 0; i < 32; i += 8)
        tile[ty + i][tx] = W[(size_t)(by + ty + i) * DM + bx + tx];
    __syncthreads();
#pragma unroll
    for (int i = 0; i < 32; i += 8) {
        float v = tile[tx][ty + i];
        __nv_bfloat16 h, l;
        split_bf16(v, h, l);
        Th[(size_t)(bx + ty + i) * DM + by + tx] = h;
        Tl[(size_t)(bx + ty + i) * DM + by + tx] = l;
    }
}

// ---------------- V fp32 [b,kv,h,d] -> transposed split [bh][d][kv] bf16 --------
__global__ void vconv_kernel() {
    __shared__ float tile[32][33];
    int bh = blockIdx.z;
    int b = bh >> 4, h = bh & 15;
    int kv0 = blockIdx.x * 32, d0 = blockIdx.y * 32;
    int tx = threadIdx.x, ty = threadIdx.y;
#pragma unroll
    for (int i = 0; i < 32; i += 8)
        tile[ty + i][tx] = g_V[(size_t)(b * NKV + kv0 + ty + i) * DM + h * DH + d0 + tx];
    __syncthreads();
#pragma unroll
    for (int i = 0; i < 32; i += 8) {
        float v = tile[tx][ty + i];
        __nv_bfloat16 h2, l2;
        split_bf16(v, h2, l2);
        size_t o = ((size_t)bh * DH + d0 + ty + i) * NKV + kv0 + tx;
        g_Vth[o] = h2; g_Vtl[o] = l2;
    }
}

// ================= HMMA GEMM: C[M,1024] = (Ah+Al)@(Bh+Bl)^T + bias ==============
#define GS_AH 0
#define GS_AL 16384
#define GS_BH 32768
#define GS_BL 49152
#define GS_TOTAL 65536

__global__ __launch_bounds__(256, 2) void gemm_mma(
    const __nv_bfloat16* __restrict__ Ah, const __nv_bfloat16* __restrict__ Al,
    const __nv_bfloat16* __restrict__ Bh, const __nv_bfloat16* __restrict__ Bl,
    const float* __restrict__ bias, float* __restrict__ C,
    __nv_bfloat16* __restrict__ Ch, __nv_bfloat16* __restrict__ Cl) {
    extern __shared__ char smem[];
    uint32_t sb = smem_u32(smem);
    int t = threadIdx.x, lane = t & 31, wid = t >> 5;
    int wm = wid & 1, wn = wid >> 1;
    int m0 = blockIdx.y * 128, n0 = blockIdx.x * 128;

    float acc[4][4][4];
#pragma unroll
    for (int i = 0; i < 4; i++)
#pragma unroll
        for (int j = 0; j < 4; j++)
#pragma unroll
            for (int k = 0; k < 4; k++) acc[i][j][k] = 0.0f;

    for (int kt = 0; kt < 16; kt++) {
        int kg = kt * 64;
        if (kt > 0) __syncthreads();
#pragma unroll
        for (int i = 0; i < 4; i++) {
            int id = i * 256 + t;
            int r = id >> 3, c8 = id & 7;
            uint32_t off = (uint32_t)(r * 128 + ((c8 ^ (r & 7)) << 4));
            *(uint4*)(smem + GS_AH + off) = *(const uint4*)(Ah + (size_t)(m0 + r) * DM + kg + c8 * 8);
            *(uint4*)(smem + GS_AL + off) = *(const uint4*)(Al + (size_t)(m0 + r) * DM + kg + c8 * 8);
            *(uint4*)(smem + GS_BH + off) = *(const uint4*)(Bh + (size_t)(n0 + r) * DM + kg + c8 * 8);
            *(uint4*)(smem + GS_BL + off) = *(const uint4*)(Bl + (size_t)(n0 + r) * DM + kg + c8 * 8);
        }
        __syncthreads();
#pragma unroll
        for (int ks = 0; ks < 4; ks++) {
            int c0 = ks * 2;
            uint32_t bh[2][4], bl[2][4];
#pragma unroll
            for (int j = 0; j < 2; j++) {
                int rowb = wn * 32 + j * 16 + (lane & 15);
                int ch = c0 + (lane >> 4);
                uint32_t so = (uint32_t)(rowb * 128 + ((ch ^ (rowb & 7)) << 4));
                ldsm4(bh[j], sb + GS_BH + so);
                ldsm4(bl[j], sb + GS_BL + so);
            }
#pragma unroll
            for (int mi = 0; mi < 4; mi++) {
                int rowa = wm * 64 + mi * 16 + (lane & 15);
                int ch = c0 + (lane >> 4);
                uint32_t so = (uint32_t)(rowa * 128 + ((ch ^ (rowa & 7)) << 4));
                uint32_t ah[4], al[4];
                ldsm4(ah, sb + GS_AH + so);
                ldsm4(al, sb + GS_AL + so);
#pragma unroll
                for (int ni = 0; ni < 4; ni++) {
                    int j = ni >> 1, s = ni & 1;
                    mma16816(acc[mi][ni], ah, bh[j][s], bh[j][s + 2]);
                    mma16816(acc[mi][ni], ah, bl[j][s], bl[j][s + 2]);
                    mma16816(acc[mi][ni], al, bh[j][s], bh[j][s + 2]);
                }
            }
        }
    }

#pragma unroll
    for (int mi = 0; mi < 4; mi++) {
#pragma unroll
        for (int ni = 0; ni < 4; ni++) {
            int m = m0 + wm * 64 + mi * 16 + (lane >> 2);
            int n = n0 + wn * 32 + ni * 8 + (lane & 3) * 2;
            float2 bv = *(const float2*)(bias + n);
            float2 v0 = make_float2(acc[mi][ni][0] + bv.x, acc[mi][ni][1] + bv.y);
            float2 v1 = make_float2(acc[mi][ni][2] + bv.x, acc[mi][ni][3] + bv.y);
            if (C) {
                *(float2*)(C + (size_t)m * DM + n) = v0;
                *(float2*)(C + (size_t)(m + 8) * DM + n) = v1;
            }
            if (Ch) {
                __nv_bfloat16 h0, l0, h1, l1;
                split_bf16(v0.x, h0, l0); split_bf16(v0.y, h1, l1);
                *(__nv_bfloat162*)(Ch + (size_t)m * DM + n) = __nv_bfloat162(h0, h1);
                *(__nv_bfloat162*)(Cl + (size_t)m * DM + n) = __nv_bfloat162(l0, l1);
                split_bf16(v1.x, h0, l0); split_bf16(v1.y, h1, l1);
                *(__nv_bfloat162*)(Ch + (size_t)(m + 8) * DM + n) = __nv_bfloat162(h0, h1);
                *(__nv_bfloat162*)(Cl + (size_t)(m + 8) * DM + n) = __nv_bfloat162(l0, l1);
            }
        }
    }
}

// == qk HMMA (RMW): attn[bh][q][k] = mask ? attn_prev + (Q.K)*SCALE : -inf ======
__global__ __launch_bounds__(256, 2) void qk_mma(float* __restrict__ attn) {
    extern __shared__ char smem[];
    uint32_t sb = smem_u32(smem);
    const int SA_H = 0, SA_L = 16384, SB_H = 32768, SB_L = 49152;
    int t = threadIdx.x, lane = t & 31, wid = t >> 5;
    int wm = wid & 1, wn = wid >> 1;
    int bhead = blockIdx.z;
    int b = bhead >> 4, h = bhead & 15;
    int q0 = blockIdx.y * 128, k0 = blockIdx.x * 128;

#pragma unroll
    for (int i = 0; i < 4; i++) {
        int id = i * 256 + t;
        int r = id >> 3, c8 = id & 7;
        uint32_t off = (uint32_t)(r * 128 + ((c8 ^ (r & 7)) << 4));
        size_t qa = (size_t)(b * NQ + q0 + r) * DM + h * DH + c8 * 8;
        size_t ka = (size_t)(b * NKV + k0 + r) * DM + h * DH + c8 * 8;
        *(uint4*)(smem + SA_H + off) = *(const uint4*)(g_Qh + qa);
        *(uint4*)(smem + SA_L + off) = *(const uint4*)(g_Ql + qa);
        *(uint4*)(smem + SB_H + off) = *(const uint4*)(g_Kh + ka);
        *(uint4*)(smem + SB_L + off) = *(const uint4*)(g_Kl + ka);
    }
    __syncthreads();

    float acc[4][4][4];
#pragma unroll
    for (int i = 0; i < 4; i++)
#pragma unroll
        for (int j = 0; j < 4; j++)
#pragma unroll
            for (int k = 0; k < 4; k++) acc[i][j][k] = 0.0f;

#pragma unroll
    for (int ks = 0; ks < 4; ks++) {
        int c0 = ks * 2;
        uint32_t bh2[2][4], bl2[2][4];
#pragma unroll
        for (int j = 0; j < 2; j++) {
            int rowb = wn * 32 + j * 16 + (lane & 15);
            int ch = c0 + (lane >> 4);
            uint32_t so = (uint32_t)(rowb * 128 + ((ch ^ (rowb & 7)) << 4));
            ldsm4(bh2[j], sb + SB_H + so);
            ldsm4(bl2[j], sb + SB_L + so);
        }
#pragma unroll
        for (int mi = 0; mi < 4; mi++) {
            int rowa = wm * 64 + mi * 16 + (lane & 15);
            int ch = c0 + (lane >> 4);
            uint32_t so = (uint32_t)(rowa * 128 + ((ch ^ (rowa & 7)) << 4));
            uint32_t ah[4], al[4];
            ldsm4(ah, sb + SA_H + so);
            ldsm4(al, sb + SA_L + so);
#pragma unroll
            for (int ni = 0; ni < 4; ni++) {
                int j = ni >> 1, s = ni & 1;
                mma16816(acc[mi][ni], ah, bh2[j][s], bh2[j][s + 2]);
                mma16816(acc[mi][ni], ah, bl2[j][s], bl2[j][s + 2]);
                mma16816(acc[mi][ni], al, bh2[j][s], bh2[j][s + 2]);
            }
        }
    }

#pragma unroll
    for (int mi = 0; mi < 4; mi++) {
#pragma unroll
        for (int ni = 0; ni < 4; ni++) {
            int m = q0 + wm * 64 + mi * 16 + (lane >> 2);
            int n = k0 + wn * 32 + ni * 8 + (lane & 3) * 2;
            float m0v = g_mask[b * NKV + n], m1v = g_mask[b * NKV + n + 1];
            float* p0 = attn + ((size_t)bhead * NQ + m) * NKV + n;
            float* p1 = attn + ((size_t)bhead * NQ + m + 8) * NKV + n;
            float2 r0 = *(float2*)p0, r1 = *(float2*)p1;
            float2 v0, v1;
            v0.x = m0v != 0.0f ? r0.x + acc[mi][ni][0] * SCALE : -INFINITY;
            v0.y = m1v != 0.0f ? r0.y + acc[mi][ni][1] * SCALE : -INFINITY;
            v1.x = m0v != 0.0f ? r1.x + acc[mi][ni][2] * SCALE : -INFINITY;
            v1.y = m1v != 0.0f ? r1.y + acc[mi][ni][3] * SCALE : -INFINITY;
            *(float2*)p0 = v0;
            *(float2*)p1 = v1;
        }
    }
}

// ===== rpe HMMA (pure store): attn[bh][q][k] = SCALE * Qh . rpe_bf16 ===========
__global__ __launch_bounds__(128) void rpe_mma(const float* __restrict__ rpe,
                                               float* __restrict__ attn) {
    __shared__ __nv_bfloat16 Rp[128 * 64];   // [k][d] swizzled, 16KB
    __shared__ __nv_bfloat16 Qs[32 * 64];    // [bh][d] swizzled, 4KB
    uint32_t sRp = smem_u32(Rp), sQs = smem_u32(Qs);
    int t = threadIdx.x, lane = t & 31, w = t >> 5;
    int q = blockIdx.y;
    int k0 = blockIdx.x * 128;

    const float4* gr = (const float4*)(rpe + ((size_t)q * NKV + k0) * DH);
#pragma unroll
    for (int i = 0; i < 16; i++) {
        int idx = i * 128 + t;
        int r = idx >> 4, c4 = idx & 15;
        float4 v = gr[idx];
        __nv_bfloat16 bv[4] = {__float2bfloat16_rn(v.x), __float2bfloat16_rn(v.y),
                               __float2bfloat16_rn(v.z), __float2bfloat16_rn(v.w)};
        int c8 = c4 >> 1, half = c4 & 1;
        *(uint2*)((char*)Rp + r * 128 + ((c8 ^ (r & 7)) << 4) + half * 8) = *(uint2*)bv;
    }
#pragma unroll
    for (int i = 0; i < 2; i++) {
        int id = i * 128 + t;
        int r = id >> 3, c8 = id & 7;
        int b = r >> 4, h = r & 15;
        *(uint4*)((char*)Qs + r * 128 + ((c8 ^ (r & 7)) << 4)) =
            *(const uint4*)(g_Qh + (size_t)(b * NQ + q) * DM + h * DH + c8 * 8);
    }
    __syncthreads();

    float acc[2][4][4];
#pragma unroll
    for (int i = 0; i < 2; i++)
#pragma unroll
        for (int j = 0; j < 4; j++)
#pragma unroll
            for (int k = 0; k < 4; k++) acc[i][j][k] = 0.0f;

#pragma unroll
    for (int ks = 0; ks < 4; ks++) {
        int c0 = ks * 2;
        uint32_t bf[2][4];
#pragma unroll
        for (int j = 0; j < 2; j++) {
            int rowb = w * 32 + j * 16 + (lane & 15);
            int ch = c0 + (lane >> 4);
            ldsm4(bf[j], sRp + (uint32_t)(rowb * 128 + ((ch ^ (rowb & 7)) << 4)));
        }
#pragma unroll
        for (int mi = 0; mi < 2; mi++) {
            int rowa = mi * 16 + (lane & 15);
            int ch = c0 + (lane >> 4);
            uint32_t af[4];
            ldsm4(af, sQs + (uint32_t)(rowa * 128 + ((ch ^ (rowa & 7)) << 4)));
#pragma unroll
            for (int ni = 0; ni < 4; ni++) {
                int j = ni >> 1, s = ni & 1;
                mma16816(acc[mi][ni], af, bf[j][s], bf[j][s + 2]);
            }
        }
    }

#pragma unroll
    for (int mi = 0; mi < 2; mi++) {
#pragma unroll
        for (int ni = 0; ni < 4; ni++) {
            int m = mi * 16 + (lane >> 2);           // bh
            int n = k0 + w * 32 + ni * 8 + (lane & 3) * 2;
            *(float2*)(attn + ((size_t)m * NQ + q) * NKV + n) =
                make_float2(SCALE * acc[mi][ni][0], SCALE * acc[mi][ni][1]);
            *(float2*)(attn + ((size_t)(m + 8) * NQ + q) * NKV + n) =
                make_float2(SCALE * acc[mi][ni][2], SCALE * acc[mi][ni][3]);
        }
    }
}

// ---------------- softmax (in place, warp-shuffle reductions) ----------------
__global__ void softmax_kernel(float* __restrict__ attn) {
    __shared__ float wm[8], ws[8];
    size_t row = blockIdx.x;
    float4* p = (float4*)(attn + row * (size_t)NKV);
    int t = threadIdx.x, lane = t & 31, w = t >> 5;
    float4 v1 = p[t], v2 = p[t + 256];
    float m = fmaxf(fmaxf(fmaxf(v1.x, v1.y), fmaxf(v1.z, v1.w)),
                    fmaxf(fmaxf(v2.x, v2.y), fmaxf(v2.z, v2.w)));
#pragma unroll
    for (int o = 16; o > 0; o >>= 1) m = fmaxf(m, __shfl_xor_sync(0xffffffffu, m, o));
    if (lane == 0) wm[w] = m;
    __syncthreads();
    float M = fmaxf(fmaxf(fmaxf(wm[0], wm[1]), fmaxf(wm[2], wm[3])),
                    fmaxf(fmaxf(wm[4], wm[5]), fmaxf(wm[6], wm[7])));
    v1.x = __expf(v1.x - M); v1.y = __expf(v1.y - M); v1.z = __expf(v1.z - M); v1.w = __expf(v1.w - M);
    v2.x = __expf(v2.x - M); v2.y = __expf(v2.y - M); v2.z = __expf(v2.z - M); v2.w = __expf(v2.w - M);
    float s = v1.x + v1.y + v1.z + v1.w + v2.x + v2.y + v2.z + v2.w;
#pragma unroll
    for (int o = 16; o > 0; o >>= 1) s += __shfl_xor_sync(0xffffffffu, s, o);
    if (lane == 0) ws[w] = s;
    __syncthreads();
    float inv = 1.0f / (ws[0] + ws[1] + ws[2] + ws[3] + ws[4] + ws[5] + ws[6] + ws[7]);
    v1.x *= inv; v1.y *= inv; v1.z *= inv; v1.w *= inv;
    v2.x *= inv; v2.y *= inv; v2.z *= inv; v2.w *= inv;
    p[t] = v1;
    p[t + 256] = v2;
}

// == av HMMA: read fp32 probs, split hi/lo in smem fill; ctx -> bf16 hi/lo ======
__global__ __launch_bounds__(256, 2) void av_mma(const float* __restrict__ attn) {
    extern __shared__ char smem[];
    uint32_t sb = smem_u32(smem);
    const int SA_H = 0, SA_L = 16384, SB_H = 32768, SB_L = 40960;
    int t = threadIdx.x, lane = t & 31, wid = t >> 5;
    int wm = wid >> 1, wn = wid & 1;
    int bhead = blockIdx.y;
    int b = bhead >> 4, h = bhead & 15;
    int q0 = blockIdx.x * 128;

    float acc[2][4][4];
#pragma unroll
    for (int i = 0; i < 2; i++)
#pragma unroll
        for (int j = 0; j < 4; j++)
#pragma unroll
            for (int k = 0; k < 4; k++) acc[i][j][k] = 0.0f;

    for (int kt = 0; kt < 32; kt++) {
        int kg = kt * 64;
        if (kt > 0) __syncthreads();
#pragma unroll
        for (int i = 0; i < 8; i++) {
            int idx = i * 256 + t;
            int r = idx >> 4, c4 = idx & 15;
            float4 v = *(const float4*)(attn + ((size_t)bhead * NQ + q0 + r) * NKV + kg + c4 * 4);
            __nv_bfloat16 hh[4], ll[4];
            split_bf16(v.x, hh[0], ll[0]); split_bf16(v.y, hh[1], ll[1]);
            split_bf16(v.z, hh[2], ll[2]); split_bf16(v.w, hh[3], ll[3]);
            int c8 = c4 >> 1, half = c4 & 1;
            uint32_t off = (uint32_t)(r * 128 + ((c8 ^ (r & 7)) << 4) + half * 8);
            *(uint2*)(smem + SA_H + off) = *(uint2*)hh;
            *(uint2*)(smem + SA_L + off) = *(uint2*)ll;
        }
#pragma unroll
        for (int i = 0; i < 2; i++) {
            int id2 = i * 256 + t;
            int r = id2 >> 3, c8 = id2 & 7;
            uint32_t off = (uint32_t)(r * 128 + ((c8 ^ (r & 7)) << 4));
            size_t gv = ((size_t)bhead * DH + r) * NKV + kg + c8 * 8;
            *(uint4*)(smem + SB_H + off) = *(const uint4*)(g_Vth + gv);
            *(uint4*)(smem + SB_L + off) = *(const uint4*)(g_Vtl + gv);
        }
        __syncthreads();
#pragma unroll
        for (int ks = 0; ks < 4; ks++) {
            int c0 = ks * 2;
            uint32_t bh2[2][4], bl2[2][4];
#pragma unroll
            for (int j = 0; j < 2; j++) {
                int rowb = wn * 32 + j * 16 + (lane & 15);
                int ch = c0 + (lane >> 4);
                uint32_t so = (uint32_t)(rowb * 128 + ((ch ^ (rowb & 7)) << 4));
                ldsm4(bh2[j], sb + SB_H + so);
                ldsm4(bl2[j], sb + SB_L + so);
            }
#pragma unroll
            for (int mi = 0; mi < 2; mi++) {
                int rowa = wm * 32 + mi * 16 + (lane & 15);
                int ch = c0 + (lane >> 4);
                uint32_t so = (uint32_t)(rowa * 128 + ((ch ^ (rowa & 7)) << 4));
                uint32_t ah[4], al[4];
                ldsm4(ah, sb + SA_H + so);
                ldsm4(al, sb + SA_L + so);
#pragma unroll
                for (int ni = 0; ni < 4; ni++) {
                    int j = ni >> 1, s = ni & 1;
                    mma16816(acc[mi][ni], ah, bh2[j][s], bh2[j][s + 2]);
                    mma16816(acc[mi][ni], ah, bl2[j][s], bl2[j][s + 2]);
                    mma16816(acc[mi][ni], al, bh2[j][s], bh2[j][s + 2]);
                }
            }
        }
    }

#pragma unroll
    for (int mi = 0; mi < 2; mi++) {
#pragma unroll
        for (int ni = 0; ni < 4; ni++) {
            int m = q0 + wm * 32 + mi * 16 + (lane >> 2);
            int n = wn * 32 + ni * 8 + (lane & 3) * 2;
            __nv_bfloat16 h0, l0, h1, l1;
            split_bf16(acc[mi][ni][0], h0, l0); split_bf16(acc[mi][ni][1], h1, l1);
            *(__nv_bfloat162*)(g_ctxh + (size_t)(b * NQ + m) * DM + h * DH + n) = __nv_bfloat162(h0, h1);
            *(__nv_bfloat162*)(g_ctxl + (size_t)(b * NQ + m) * DM + h * DH + n) = __nv_bfloat162(l0, l1);
            split_bf16(acc[mi][ni][2], h0, l0); split_bf16(acc[mi][ni][3], h1, l1);
            *(__nv_bfloat162*)(g_ctxh + (size_t)(b * NQ + m + 8) * DM + h * DH + n) = __nv_bfloat162(h0, h1);
            *(__nv_bfloat162*)(g_ctxl + (size_t)(b * NQ + m + 8) * DM + h * DH + n) = __nv_bfloat162(l0, l1);
        }
    }
}

// ---------------- launch ----------------
extern "C" void kernel_launch(void* const* d_in, const int* in_sizes, int n_in,
                              void* d_out, int out_size) {
    const float* q = (const float*)d_in[0];
    const float* kv = (const float*)d_in[1];
    const unsigned char* mask = (const unsigned char*)d_in[2];
    const float* rpe = (const float*)d_in[3];
    const float* Wq = (const float*)d_in[4];
    const float* bq = (const float*)d_in[5];
    const float* Wk = (const float*)d_in[6];
    const float* bk = (const float*)d_in[7];
    const float* Wv = (const float*)d_in[8];
    const float* bv = (const float*)d_in[9];
    const float* Wo = (const float*)d_in[10];
    const float* bo = (const float*)d_in[11];
    const float* lg = (const float*)d_in[12];
    const float* lb = (const float*)d_in[13];

    float* out = (float*)d_out;
    const size_t ATT = (size_t)BB * NH * NQ * NKV;
    const size_t OUTN = (size_t)BB * NQ * DM;
    float* attn;
    if ((size_t)out_size >= ATT + OUTN) {
        attn = out + ((size_t)out_size - ATT);
    } else {
        void* p;
        cudaGetSymbolAddress(&p, g_attn_fallback);
        attn = (float*)p;
    }

#define SYMF(sym) ([]{ void* p; cudaGetSymbolAddress(&p, sym); return (float*)p; }())
#define SYMB(sym) ([]{ void* p; cudaGetSymbolAddress(&p, sym); return (__nv_bfloat16*)p; }())
    float* p_V = SYMF(g_V);
    __nv_bfloat16* p_qnh = SYMB(g_qnh);   __nv_bfloat16* p_qnl = SYMB(g_qnl);
    __nv_bfloat16* p_kvnh = SYMB(g_kvnh); __nv_bfloat16* p_kvnl = SYMB(g_kvnl);
    __nv_bfloat16* p_Wqh = SYMB(g_Wqh);   __nv_bfloat16* p_Wql = SYMB(g_Wql);
    __nv_bfloat16* p_Wkh = SYMB(g_Wkh);   __nv_bfloat16* p_Wkl = SYMB(g_Wkl);
    __nv_bfloat16* p_Wvh = SYMB(g_Wvh);   __nv_bfloat16* p_Wvl = SYMB(g_Wvl);
    __nv_bfloat16* p_Woh = SYMB(g_Woh);   __nv_bfloat16* p_Wol = SYMB(g_Wol);
    __nv_bfloat16* p_ctxh = SYMB(g_ctxh); __nv_bfloat16* p_ctxl = SYMB(g_ctxl);
    __nv_bfloat16* p_Qh = SYMB(g_Qh);     __nv_bfloat16* p_Ql = SYMB(g_Ql);
    __nv_bfloat16* p_Kh = SYMB(g_Kh);     __nv_bfloat16* p_Kl = SYMB(g_Kl);

    cudaFuncSetAttribute(gemm_mma, cudaFuncAttributeMaxDynamicSharedMemorySize, GS_TOTAL);
    cudaFuncSetAttribute(qk_mma, cudaFuncAttributeMaxDynamicSharedMemorySize, 65536);
    cudaFuncSetAttribute(av_mma, cudaFuncAttributeMaxDynamicSharedMemorySize, 49152);

    // exactly ONE side stream + two events (R12-validated resource pattern)
    cudaStream_t s2;
    cudaStreamCreate(&s2);
    cudaEvent_t evFork, evJoin;
    cudaEventCreateWithFlags(&evFork, cudaEventDisableTiming);
    cudaEventCreateWithFlags(&evJoin, cudaEventDisableTiming);

    dim3 wt(32, 8);
    dim3 wg(32, 32);

    // main chain: Q path + rpe (rpe needs only Qh; writes base scores)
    mask_kernel<<<1, 256>>>(mask);
    ln_kernel<<<BB * NQ + BB * NKV, 256>>>(q, kv, lg, lb);
    cudaEventRecord(evFork, 0);

    wconv_kernel<<<wg, wt>>>(Wq, p_Wqh, p_Wql);
    gemm_mma<<<dim3(8, 16), 256, GS_TOTAL>>>(p_qnh, p_qnl, p_Wqh, p_Wql, bq, nullptr, p_Qh, p_Ql);
    rpe_mma<<<dim3(NKV / 128, NQ), 128>>>(rpe, attn);

    // s2 (serial): K path, then V path, then Wo conversion — hidden under gemmQ+rpe
    cudaStreamWaitEvent(s2, evFork, 0);
    wconv_kernel<<<wg, wt, 0, s2>>>(Wk, p_Wkh, p_Wkl);
    gemm_mma<<<dim3(8, 32), 256, GS_TOTAL, s2>>>(p_kvnh, p_kvnl, p_Wkh, p_Wkl, bk, nullptr, p_Kh, p_Kl);
    wconv_kernel<<<wg, wt, 0, s2>>>(Wv, p_Wvh, p_Wvl);
    gemm_mma<<<dim3(8, 32), 256, GS_TOTAL, s2>>>(p_kvnh, p_kvnl, p_Wvh, p_Wvl, bv, p_V, nullptr, nullptr);
    vconv_kernel<<<dim3(NKV / 32, 2, BB * NH), wt, 0, s2>>>();
    wconv_kernel<<<wg, wt, 0, s2>>>(Wo, p_Woh, p_Wol);
    cudaEventRecord(evJoin, s2);

    // join, then qk (RMW: rpe scores + K), softmax, av, output projection
    cudaStreamWaitEvent(0, evJoin, 0);
    qk_mma<<<dim3(NKV / 128, NQ / 128, BB * NH), 256, 65536>>>(attn);
    softmax_kernel<<<BB * NH * NQ, 256>>>(attn);
    av_mma<<<dim3(NQ / 128, BB * NH), 256, 49152>>>(attn);
    gemm_mma<<<dim3(8, 16), 256, GS_TOTAL>>>(p_ctxh, p_ctxl, p_Woh, p_Wol, bo, out, nullptr, nullptr);
}

// round 15
// speedup vs baseline: 1.4389x; 1.4389x over previous
#include <cuda_runtime.h>
#include <cuda_bf16.h>
#include <cstdint>
#include <math.h>

#define BB 2
#define NQ 1024
#define NKV 2048
#define DM 1024
#define NH 16
#define DH 64
#define SCALE 0.125f
#define LNEPS 1e-5f

// ================= scratch (alloc-free rule: __device__ globals) ================
__device__ __nv_bfloat16 g_qnh[BB * NQ * DM], g_qnl[BB * NQ * DM];
__device__ __nv_bfloat16 g_kvnh[BB * NKV * DM], g_kvnl[BB * NKV * DM];
__device__ __nv_bfloat16 g_Wqh[DM * DM], g_Wql[DM * DM];
__device__ __nv_bfloat16 g_Wkh[DM * DM], g_Wkl[DM * DM];
__device__ __nv_bfloat16 g_Wvh[DM * DM], g_Wvl[DM * DM];
__device__ __nv_bfloat16 g_Woh[DM * DM], g_Wol[DM * DM];
__device__ __nv_bfloat16 g_ctxh[BB * NQ * NH * DH], g_ctxl[BB * NQ * NH * DH];
__device__ __nv_bfloat16 g_Qh[BB * NQ * DM], g_Ql[BB * NQ * DM];
__device__ __nv_bfloat16 g_Kh[BB * NKV * DM], g_Kl[BB * NKV * DM];
__device__ __nv_bfloat16 g_Vth[BB * NH * DH * NKV], g_Vtl[BB * NH * DH * NKV]; // [bh][d][kv]
__device__ float g_V[BB * NKV * NH * DH];
__device__ float g_mask[BB * NKV];
__device__ float g_attn_fallback[(size_t)BB * NH * NQ * NKV];

__device__ __forceinline__ void split_bf16(float x, __nv_bfloat16& h, __nv_bfloat16& l) {
    h = __float2bfloat16_rn(x);
    l = __float2bfloat16_rn(x - __bfloat162float(h));
}
__device__ __forceinline__ uint32_t smem_u32(const void* p) {
    uint32_t a;
    asm("{ .reg .u64 t; cvta.to.shared.u64 t, %1; cvt.u32.u64 %0, t; }" : "=r"(a) : "l"(p));
    return a;
}
__device__ __forceinline__ void ldsm4(uint32_t* d, uint32_t addr) {
    asm volatile("ldmatrix.sync.aligned.m8n8.x4.shared.b16 {%0,%1,%2,%3}, [%4];"
                 : "=r"(d[0]), "=r"(d[1]), "=r"(d[2]), "=r"(d[3]) : "r"(addr));
}
__device__ __forceinline__ void mma16816(float* c, const uint32_t* a, uint32_t b0, uint32_t b1) {
    asm volatile("mma.sync.aligned.m16n8k16.row.col.f32.bf16.bf16.f32 "
                 "{%0,%1,%2,%3}, {%4,%5,%6,%7}, {%8,%9}, {%0,%1,%2,%3};"
                 : "+f"(c[0]), "+f"(c[1]), "+f"(c[2]), "+f"(c[3])
                 : "r"(a[0]), "r"(a[1]), "r"(a[2]), "r"(a[3]), "r"(b0), "r"(b1));
}

// ---------------- mask normalization: dtype-agnostic ------
__global__ void mask_kernel(const unsigned char* __restrict__ m) {
    __shared__ int s_ge2, s_off;
    int t = threadIdx.x;
    if (t == 0) { s_ge2 = 0; s_off = 0; }
    __syncthreads();
    int ge2 = 0, off = 0;
    for (int i = t; i < BB * NKV; i += 256) {
        unsigned char b = m[i];
        if (b >= 2) ge2 = 1;
        if ((i & 3) && b) off = 1;
    }
    if (ge2) atomicOr(&s_ge2, 1);
    if (off) atomicOr(&s_off, 1);
    __syncthreads();
    int kind = s_ge2 ? 2 : (s_off ? 0 : 1);
    for (int i = t; i < BB * NKV; i += 256) {
        float v;
        if (kind == 2)      v = (((const float*)m)[i] != 0.0f) ? 1.0f : 0.0f;
        else if (kind == 1) v = (((const int*)m)[i] != 0) ? 1.0f : 0.0f;
        else                v = (m[i] != 0) ? 1.0f : 0.0f;
        g_mask[i] = v;
    }
}

// ---------------- LayerNorm -> bf16 hi/lo ----------------
__global__ void ln_kernel(const float* __restrict__ q, const float* __restrict__ kv,
                          const float* __restrict__ gam, const float* __restrict__ bet) {
    __shared__ float red[256];
    int row = blockIdx.x;
    const float* src;
    __nv_bfloat16 *dh, *dl;
    if (row < BB * NQ) {
        src = q + (size_t)row * DM;
        dh = g_qnh + (size_t)row * DM; dl = g_qnl + (size_t)row * DM;
    } else {
        int r = row - BB * NQ;
        src = kv + (size_t)r * DM;
        dh = g_kvnh + (size_t)r * DM; dl = g_kvnl + (size_t)r * DM;
    }
    int t = threadIdx.x;
    float4 x = ((const float4*)src)[t];
    red[t] = x.x + x.y + x.z + x.w;
    __syncthreads();
    for (int o = 128; o > 0; o >>= 1) { if (t < o) red[t] += red[t + o]; __syncthreads(); }
    float mu = red[0] * (1.0f / DM);
    __syncthreads();
    float dx = x.x - mu, dy = x.y - mu, dz = x.z - mu, dw = x.w - mu;
    red[t] = dx * dx + dy * dy + dz * dz + dw * dw;
    __syncthreads();
    for (int o = 128; o > 0; o >>= 1) { if (t < o) red[t] += red[t + o]; __syncthreads(); }
    float rstd = rsqrtf(red[0] * (1.0f / DM) + LNEPS);
    float4 g4 = ((const float4*)gam)[t];
    float4 b4 = ((const float4*)bet)[t];
    float o0 = dx * rstd * g4.x + b4.x;
    float o1 = dy * rstd * g4.y + b4.y;
    float o2 = dz * rstd * g4.z + b4.z;
    float o3 = dw * rstd * g4.w + b4.w;
    __nv_bfloat16 h[4], l[4];
    split_bf16(o0, h[0], l[0]); split_bf16(o1, h[1], l[1]);
    split_bf16(o2, h[2], l[2]); split_bf16(o3, h[3], l[3]);
    *(uint2*)(dh + 4 * t) = *(uint2*)h;
    *(uint2*)(dl + 4 * t) = *(uint2*)l;
}

// ---------------- weight transpose + bf16 split ----------------
__global__ void wconv_kernel(const float* __restrict__ W,
                             __nv_bfloat16* __restrict__ Th, __nv_bfloat16* __restrict__ Tl) {
    __shared__ float tile[32][33];
    int bx = blockIdx.x * 32;  // n
    int by = blockIdx.y * 32;  // k
    int tx = threadIdx.x, ty = threadIdx.y;
#pragma unroll
    for (int i = 0; i < 32; i += 8)
        tile[ty + i][tx] = W[(size_t)(by + ty + i) * DM + bx + tx];
    __syncthreads();
#pragma unroll
    for (int i = 0; i < 32; i += 8) {
        float v = tile[tx][ty + i];
        __nv_bfloat16 h, l;
        split_bf16(v, h, l);
        Th[(size_t)(bx + ty + i) * DM + by + tx] = h;
        Tl[(size_t)(bx + ty + i) * DM + by + tx] = l;
    }
}

// ---------------- V fp32 [b,kv,h,d] -> transposed split [bh][d][kv] bf16 --------
__global__ void vconv_kernel() {
    __shared__ float tile[32][33];
    int bh = blockIdx.z;
    int b = bh >> 4, h = bh & 15;
    int kv0 = blockIdx.x * 32, d0 = blockIdx.y * 32;
    int tx = threadIdx.x, ty = threadIdx.y;
#pragma unroll
    for (int i = 0; i < 32; i += 8)
        tile[ty + i][tx] = g_V[(size_t)(b * NKV + kv0 + ty + i) * DM + h * DH + d0 + tx];
    __syncthreads();
#pragma unroll
    for (int i = 0; i < 32; i += 8) {
        float v = tile[tx][ty + i];
        __nv_bfloat16 h2, l2;
        split_bf16(v, h2, l2);
        size_t o = ((size_t)bh * DH + d0 + ty + i) * NKV + kv0 + tx;
        g_Vth[o] = h2; g_Vtl[o] = l2;
    }
}

// ================= HMMA GEMM: C[M,1024] = (Ah+Al)@(Bh+Bl)^T + bias ==============
#define GS_AH 0
#define GS_AL 16384
#define GS_BH 32768
#define GS_BL 49152
#define GS_TOTAL 65536

__global__ __launch_bounds__(256, 2) void gemm_mma(
    const __nv_bfloat16* __restrict__ Ah, const __nv_bfloat16* __restrict__ Al,
    const __nv_bfloat16* __restrict__ Bh, const __nv_bfloat16* __restrict__ Bl,
    const float* __restrict__ bias, float* __restrict__ C,
    __nv_bfloat16* __restrict__ Ch, __nv_bfloat16* __restrict__ Cl) {
    extern __shared__ char smem[];
    uint32_t sb = smem_u32(smem);
    int t = threadIdx.x, lane = t & 31, wid = t >> 5;
    int wm = wid & 1, wn = wid >> 1;
    int m0 = blockIdx.y * 128, n0 = blockIdx.x * 128;

    float acc[4][4][4];
#pragma unroll
    for (int i = 0; i < 4; i++)
#pragma unroll
        for (int j = 0; j < 4; j++)
#pragma unroll
            for (int k = 0; k < 4; k++) acc[i][j][k] = 0.0f;

    for (int kt = 0; kt < 16; kt++) {
        int kg = kt * 64;
        if (kt > 0) __syncthreads();
#pragma unroll
        for (int i = 0; i < 4; i++) {
            int id = i * 256 + t;
            int r = id >> 3, c8 = id & 7;
            uint32_t off = (uint32_t)(r * 128 + ((c8 ^ (r & 7)) << 4));
            *(uint4*)(smem + GS_AH + off) = *(const uint4*)(Ah + (size_t)(m0 + r) * DM + kg + c8 * 8);
            *(uint4*)(smem + GS_AL + off) = *(const uint4*)(Al + (size_t)(m0 + r) * DM + kg + c8 * 8);
            *(uint4*)(smem + GS_BH + off) = *(const uint4*)(Bh + (size_t)(n0 + r) * DM + kg + c8 * 8);
            *(uint4*)(smem + GS_BL + off) = *(const uint4*)(Bl + (size_t)(n0 + r) * DM + kg + c8 * 8);
        }
        __syncthreads();
#pragma unroll
        for (int ks = 0; ks < 4; ks++) {
            int c0 = ks * 2;
            uint32_t bh[2][4], bl[2][4];
#pragma unroll
            for (int j = 0; j < 2; j++) {
                int rowb = wn * 32 + j * 16 + (lane & 15);
                int ch = c0 + (lane >> 4);
                uint32_t so = (uint32_t)(rowb * 128 + ((ch ^ (rowb & 7)) << 4));
                ldsm4(bh[j], sb + GS_BH + so);
                ldsm4(bl[j], sb + GS_BL + so);
            }
#pragma unroll
            for (int mi = 0; mi < 4; mi++) {
                int rowa = wm * 64 + mi * 16 + (lane & 15);
                int ch = c0 + (lane >> 4);
                uint32_t so = (uint32_t)(rowa * 128 + ((ch ^ (rowa & 7)) << 4));
                uint32_t ah[4], al[4];
                ldsm4(ah, sb + GS_AH + so);
                ldsm4(al, sb + GS_AL + so);
#pragma unroll
                for (int ni = 0; ni < 4; ni++) {
                    int j = ni >> 1, s = ni & 1;
                    mma16816(acc[mi][ni], ah, bh[j][s], bh[j][s + 2]);
                    mma16816(acc[mi][ni], ah, bl[j][s], bl[j][s + 2]);
                    mma16816(acc[mi][ni], al, bh[j][s], bh[j][s + 2]);
                }
            }
        }
    }

#pragma unroll
    for (int mi = 0; mi < 4; mi++) {
#pragma unroll
        for (int ni = 0; ni < 4; ni++) {
            int m = m0 + wm * 64 + mi * 16 + (lane >> 2);
            int n = n0 + wn * 32 + ni * 8 + (lane & 3) * 2;
            float2 bv = *(const float2*)(bias + n);
            float2 v0 = make_float2(acc[mi][ni][0] + bv.x, acc[mi][ni][1] + bv.y);
            float2 v1 = make_float2(acc[mi][ni][2] + bv.x, acc[mi][ni][3] + bv.y);
            if (C) {
                *(float2*)(C + (size_t)m * DM + n) = v0;
                *(float2*)(C + (size_t)(m + 8) * DM + n) = v1;
            }
            if (Ch) {
                __nv_bfloat16 h0, l0, h1, l1;
                split_bf16(v0.x, h0, l0); split_bf16(v0.y, h1, l1);
                *(__nv_bfloat162*)(Ch + (size_t)m * DM + n) = __nv_bfloat162(h0, h1);
                *(__nv_bfloat162*)(Cl + (size_t)m * DM + n) = __nv_bfloat162(l0, l1);
                split_bf16(v1.x, h0, l0); split_bf16(v1.y, h1, l1);
                *(__nv_bfloat162*)(Ch + (size_t)(m + 8) * DM + n) = __nv_bfloat162(h0, h1);
                *(__nv_bfloat162*)(Cl + (size_t)(m + 8) * DM + n) = __nv_bfloat162(l0, l1);
            }
        }
    }
}

// ================= qk HMMA: attn[bh][q][k] = mask ? (Q.K)*SCALE : -inf =========
__global__ __launch_bounds__(256, 2) void qk_mma(float* __restrict__ attn) {
    extern __shared__ char smem[];
    uint32_t sb = smem_u32(smem);
    const int SA_H = 0, SA_L = 16384, SB_H = 32768, SB_L = 49152;
    int t = threadIdx.x, lane = t & 31, wid = t >> 5;
    int wm = wid & 1, wn = wid >> 1;
    int bhead = blockIdx.z;
    int b = bhead >> 4, h = bhead & 15;
    int q0 = blockIdx.y * 128, k0 = blockIdx.x * 128;

#pragma unroll
    for (int i = 0; i < 4; i++) {
        int id = i * 256 + t;
        int r = id >> 3, c8 = id & 7;
        uint32_t off = (uint32_t)(r * 128 + ((c8 ^ (r & 7)) << 4));
        size_t qa = (size_t)(b * NQ + q0 + r) * DM + h * DH + c8 * 8;
        size_t ka = (size_t)(b * NKV + k0 + r) * DM + h * DH + c8 * 8;
        *(uint4*)(smem + SA_H + off) = *(const uint4*)(g_Qh + qa);
        *(uint4*)(smem + SA_L + off) = *(const uint4*)(g_Ql + qa);
        *(uint4*)(smem + SB_H + off) = *(const uint4*)(g_Kh + ka);
        *(uint4*)(smem + SB_L + off) = *(const uint4*)(g_Kl + ka);
    }
    __syncthreads();

    float acc[4][4][4];
#pragma unroll
    for (int i = 0; i < 4; i++)
#pragma unroll
        for (int j = 0; j < 4; j++)
#pragma unroll
            for (int k = 0; k < 4; k++) acc[i][j][k] = 0.0f;

#pragma unroll
    for (int ks = 0; ks < 4; ks++) {
        int c0 = ks * 2;
        uint32_t bh2[2][4], bl2[2][4];
#pragma unroll
        for (int j = 0; j < 2; j++) {
            int rowb = wn * 32 + j * 16 + (lane & 15);
            int ch = c0 + (lane >> 4);
            uint32_t so = (uint32_t)(rowb * 128 + ((ch ^ (rowb & 7)) << 4));
            ldsm4(bh2[j], sb + SB_H + so);
            ldsm4(bl2[j], sb + SB_L + so);
        }
#pragma unroll
        for (int mi = 0; mi < 4; mi++) {
            int rowa = wm * 64 + mi * 16 + (lane & 15);
            int ch = c0 + (lane >> 4);
            uint32_t so = (uint32_t)(rowa * 128 + ((ch ^ (rowa & 7)) << 4));
            uint32_t ah[4], al[4];
            ldsm4(ah, sb + SA_H + so);
            ldsm4(al, sb + SA_L + so);
#pragma unroll
            for (int ni = 0; ni < 4; ni++) {
                int j = ni >> 1, s = ni & 1;
                mma16816(acc[mi][ni], ah, bh2[j][s], bh2[j][s + 2]);
                mma16816(acc[mi][ni], ah, bl2[j][s], bl2[j][s + 2]);
                mma16816(acc[mi][ni], al, bh2[j][s], bh2[j][s + 2]);
            }
        }
    }

#pragma unroll
    for (int mi = 0; mi < 4; mi++) {
#pragma unroll
        for (int ni = 0; ni < 4; ni++) {
            int m = q0 + wm * 64 + mi * 16 + (lane >> 2);
            int n = k0 + wn * 32 + ni * 8 + (lane & 3) * 2;
            float m0v = g_mask[b * NKV + n], m1v = g_mask[b * NKV + n + 1];
            float2 v0, v1;
            v0.x = m0v != 0.0f ? acc[mi][ni][0] * SCALE : -INFINITY;
            v0.y = m1v != 0.0f ? acc[mi][ni][1] * SCALE : -INFINITY;
            v1.x = m0v != 0.0f ? acc[mi][ni][2] * SCALE : -INFINITY;
            v1.y = m1v != 0.0f ? acc[mi][ni][3] * SCALE : -INFINITY;
            *(float2*)(attn + ((size_t)bhead * NQ + m) * NKV + n) = v0;
            *(float2*)(attn + ((size_t)bhead * NQ + m + 8) * NKV + n) = v1;
        }
    }
}

// ================= rpe HMMA: attn[bh][q][k] += SCALE * Qh . rpe_bf16 ===========
__global__ __launch_bounds__(128) void rpe_mma(const float* __restrict__ rpe,
                                               float* __restrict__ attn) {
    __shared__ __nv_bfloat16 Rp[128 * 64];   // [k][d] swizzled, 16KB
    __shared__ __nv_bfloat16 Qs[32 * 64];    // [bh][d] swizzled, 4KB
    uint32_t sRp = smem_u32(Rp), sQs = smem_u32(Qs);
    int t = threadIdx.x, lane = t & 31, w = t >> 5;
    int q = blockIdx.y;
    int k0 = blockIdx.x * 128;

    const float4* gr = (const float4*)(rpe + ((size_t)q * NKV + k0) * DH);
#pragma unroll
    for (int i = 0; i < 16; i++) {
        int idx = i * 128 + t;
        int r = idx >> 4, c4 = idx & 15;
        float4 v = gr[idx];
        __nv_bfloat16 bv[4] = {__float2bfloat16_rn(v.x), __float2bfloat16_rn(v.y),
                               __float2bfloat16_rn(v.z), __float2bfloat16_rn(v.w)};
        int c8 = c4 >> 1, half = c4 & 1;
        *(uint2*)((char*)Rp + r * 128 + ((c8 ^ (r & 7)) << 4) + half * 8) = *(uint2*)bv;
    }
#pragma unroll
    for (int i = 0; i < 2; i++) {
        int id = i * 128 + t;
        int r = id >> 3, c8 = id & 7;
        int b = r >> 4, h = r & 15;
        *(uint4*)((char*)Qs + r * 128 + ((c8 ^ (r & 7)) << 4)) =
            *(const uint4*)(g_Qh + (size_t)(b * NQ + q) * DM + h * DH + c8 * 8);
    }
    __syncthreads();

    float acc[2][4][4];
#pragma unroll
    for (int i = 0; i < 2; i++)
#pragma unroll
        for (int j = 0; j < 4; j++)
#pragma unroll
            for (int k = 0; k < 4; k++) acc[i][j][k] = 0.0f;

#pragma unroll
    for (int ks = 0; ks < 4; ks++) {
        int c0 = ks * 2;
        uint32_t bf[2][4];
#pragma unroll
        for (int j = 0; j < 2; j++) {
            int rowb = w * 32 + j * 16 + (lane & 15);
            int ch = c0 + (lane >> 4);
            ldsm4(bf[j], sRp + (uint32_t)(rowb * 128 + ((ch ^ (rowb & 7)) << 4)));
        }
#pragma unroll
        for (int mi = 0; mi < 2; mi++) {
            int rowa = mi * 16 + (lane & 15);
            int ch = c0 + (lane >> 4);
            uint32_t af[4];
            ldsm4(af, sQs + (uint32_t)(rowa * 128 + ((ch ^ (rowa & 7)) << 4)));
#pragma unroll
            for (int ni = 0; ni < 4; ni++) {
                int j = ni >> 1, s = ni & 1;
                mma16816(acc[mi][ni], af, bf[j][s], bf[j][s + 2]);
            }
        }
    }

#pragma unroll
    for (int mi = 0; mi < 2; mi++) {
#pragma unroll
        for (int ni = 0; ni < 4; ni++) {
            int m = mi * 16 + (lane >> 2);           // bh
            int n = k0 + w * 32 + ni * 8 + (lane & 3) * 2;
            float* p0 = attn + ((size_t)m * NQ + q) * NKV + n;
            float* p1 = attn + ((size_t)(m + 8) * NQ + q) * NKV + n;
            float2 c0v = *(float2*)p0, c1v = *(float2*)p1;
            c0v.x += SCALE * acc[mi][ni][0]; c0v.y += SCALE * acc[mi][ni][1];
            c1v.x += SCALE * acc[mi][ni][2]; c1v.y += SCALE * acc[mi][ni][3];
            *(float2*)p0 = c0v;
            *(float2*)p1 = c1v;
        }
    }
}

// ---------------- softmax (in place, warp-shuffle reductions) ----------------
__global__ void softmax_kernel(float* __restrict__ attn) {
    __shared__ float wm[8], ws[8];
    size_t row = blockIdx.x;
    float4* p = (float4*)(attn + row * (size_t)NKV);
    int t = threadIdx.x, lane = t & 31, w = t >> 5;
    float4 v1 = p[t], v2 = p[t + 256];
    float m = fmaxf(fmaxf(fmaxf(v1.x, v1.y), fmaxf(v1.z, v1.w)),
                    fmaxf(fmaxf(v2.x, v2.y), fmaxf(v2.z, v2.w)));
#pragma unroll
    for (int o = 16; o > 0; o >>= 1) m = fmaxf(m, __shfl_xor_sync(0xffffffffu, m, o));
    if (lane == 0) wm[w] = m;
    __syncthreads();
    float M = fmaxf(fmaxf(fmaxf(wm[0], wm[1]), fmaxf(wm[2], wm[3])),
                    fmaxf(fmaxf(wm[4], wm[5]), fmaxf(wm[6], wm[7])));
    v1.x = __expf(v1.x - M); v1.y = __expf(v1.y - M); v1.z = __expf(v1.z - M); v1.w = __expf(v1.w - M);
    v2.x = __expf(v2.x - M); v2.y = __expf(v2.y - M); v2.z = __expf(v2.z - M); v2.w = __expf(v2.w - M);
    float s = v1.x + v1.y + v1.z + v1.w + v2.x + v2.y + v2.z + v2.w;
#pragma unroll
    for (int o = 16; o > 0; o >>= 1) s += __shfl_xor_sync(0xffffffffu, s, o);
    if (lane == 0) ws[w] = s;
    __syncthreads();
    float inv = 1.0f / (ws[0] + ws[1] + ws[2] + ws[3] + ws[4] + ws[5] + ws[6] + ws[7]);
    v1.x *= inv; v1.y *= inv; v1.z *= inv; v1.w *= inv;
    v2.x *= inv; v2.y *= inv; v2.z *= inv; v2.w *= inv;
    p[t] = v1;
    p[t + 256] = v2;
}

// == av HMMA: read fp32 probs, split hi/lo in smem fill; ctx -> bf16 hi/lo ======
__global__ __launch_bounds__(256, 2) void av_mma(const float* __restrict__ attn) {
    extern __shared__ char smem[];
    uint32_t sb = smem_u32(smem);
    const int SA_H = 0, SA_L = 16384, SB_H = 32768, SB_L = 40960;
    int t = threadIdx.x, lane = t & 31, wid = t >> 5;
    int wm = wid >> 1, wn = wid & 1;
    int bhead = blockIdx.y;
    int b = bhead >> 4, h = bhead & 15;
    int q0 = blockIdx.x * 128;

    float acc[2][4][4];
#pragma unroll
    for (int i = 0; i < 2; i++)
#pragma unroll
        for (int j = 0; j < 4; j++)
#pragma unroll
            for (int k = 0; k < 4; k++) acc[i][j][k] = 0.0f;

    for (int kt = 0; kt < 32; kt++) {
        int kg = kt * 64;
        if (kt > 0) __syncthreads();
#pragma unroll
        for (int i = 0; i < 8; i++) {
            int idx = i * 256 + t;
            int r = idx >> 4, c4 = idx & 15;
            float4 v = *(const float4*)(attn + ((size_t)bhead * NQ + q0 + r) * NKV + kg + c4 * 4);
            __nv_bfloat16 hh[4], ll[4];
            split_bf16(v.x, hh[0], ll[0]); split_bf16(v.y, hh[1], ll[1]);
            split_bf16(v.z, hh[2], ll[2]); split_bf16(v.w, hh[3], ll[3]);
            int c8 = c4 >> 1, half = c4 & 1;
            uint32_t off = (uint32_t)(r * 128 + ((c8 ^ (r & 7)) << 4) + half * 8);
            *(uint2*)(smem + SA_H + off) = *(uint2*)hh;
            *(uint2*)(smem + SA_L + off) = *(uint2*)ll;
        }
#pragma unroll
        for (int i = 0; i < 2; i++) {
            int id2 = i * 256 + t;
            int r = id2 >> 3, c8 = id2 & 7;
            uint32_t off = (uint32_t)(r * 128 + ((c8 ^ (r & 7)) << 4));
            size_t gv = ((size_t)bhead * DH + r) * NKV + kg + c8 * 8;
            *(uint4*)(smem + SB_H + off) = *(const uint4*)(g_Vth + gv);
            *(uint4*)(smem + SB_L + off) = *(const uint4*)(g_Vtl + gv);
        }
        __syncthreads();
#pragma unroll
        for (int ks = 0; ks < 4; ks++) {
            int c0 = ks * 2;
            uint32_t bh2[2][4], bl2[2][4];
#pragma unroll
            for (int j = 0; j < 2; j++) {
                int rowb = wn * 32 + j * 16 + (lane & 15);
                int ch = c0 + (lane >> 4);
                uint32_t so = (uint32_t)(rowb * 128 + ((ch ^ (rowb & 7)) << 4));
                ldsm4(bh2[j], sb + SB_H + so);
                ldsm4(bl2[j], sb + SB_L + so);
            }
#pragma unroll
            for (int mi = 0; mi < 2; mi++) {
                int rowa = wm * 32 + mi * 16 + (lane & 15);
                int ch = c0 + (lane >> 4);
                uint32_t so = (uint32_t)(rowa * 128 + ((ch ^ (rowa & 7)) << 4));
                uint32_t ah[4], al[4];
                ldsm4(ah, sb + SA_H + so);
                ldsm4(al, sb + SA_L + so);
#pragma unroll
                for (int ni = 0; ni < 4; ni++) {
                    int j = ni >> 1, s = ni & 1;
                    mma16816(acc[mi][ni], ah, bh2[j][s], bh2[j][s + 2]);
                    mma16816(acc[mi][ni], ah, bl2[j][s], bl2[j][s + 2]);
                    mma16816(acc[mi][ni], al, bh2[j][s], bh2[j][s + 2]);
                }
            }
        }
    }

#pragma unroll
    for (int mi = 0; mi < 2; mi++) {
#pragma unroll
        for (int ni = 0; ni < 4; ni++) {
            int m = q0 + wm * 32 + mi * 16 + (lane >> 2);
            int n = wn * 32 + ni * 8 + (lane & 3) * 2;
            __nv_bfloat16 h0, l0, h1, l1;
            split_bf16(acc[mi][ni][0], h0, l0); split_bf16(acc[mi][ni][1], h1, l1);
            *(__nv_bfloat162*)(g_ctxh + (size_t)(b * NQ + m) * DM + h * DH + n) = __nv_bfloat162(h0, h1);
            *(__nv_bfloat162*)(g_ctxl + (size_t)(b * NQ + m) * DM + h * DH + n) = __nv_bfloat162(l0, l1);
            split_bf16(acc[mi][ni][2], h0, l0); split_bf16(acc[mi][ni][3], h1, l1);
            *(__nv_bfloat162*)(g_ctxh + (size_t)(b * NQ + m + 8) * DM + h * DH + n) = __nv_bfloat162(h0, h1);
            *(__nv_bfloat162*)(g_ctxl + (size_t)(b * NQ + m + 8) * DM + h * DH + n) = __nv_bfloat162(l0, l1);
        }
    }
}

// ---------------- launch ----------------
extern "C" void kernel_launch(void* const* d_in, const int* in_sizes, int n_in,
                              void* d_out, int out_size) {
    const float* q = (const float*)d_in[0];
    const float* kv = (const float*)d_in[1];
    const unsigned char* mask = (const unsigned char*)d_in[2];
    const float* rpe = (const float*)d_in[3];
    const float* Wq = (const float*)d_in[4];
    const float* bq = (const float*)d_in[5];
    const float* Wk = (const float*)d_in[6];
    const float* bk = (const float*)d_in[7];
    const float* Wv = (const float*)d_in[8];
    const float* bv = (const float*)d_in[9];
    const float* Wo = (const float*)d_in[10];
    const float* bo = (const float*)d_in[11];
    const float* lg = (const float*)d_in[12];
    const float* lb = (const float*)d_in[13];

    float* out = (float*)d_out;
    const size_t ATT = (size_t)BB * NH * NQ * NKV;
    const size_t OUTN = (size_t)BB * NQ * DM;
    float* attn;
    if ((size_t)out_size >= ATT + OUTN) {
        attn = out + ((size_t)out_size - ATT);
    } else {
        void* p;
        cudaGetSymbolAddress(&p, g_attn_fallback);
        attn = (float*)p;
    }

#define SYMF(sym) ([]{ void* p; cudaGetSymbolAddress(&p, sym); return (float*)p; }())
#define SYMB(sym) ([]{ void* p; cudaGetSymbolAddress(&p, sym); return (__nv_bfloat16*)p; }())
    float* p_V = SYMF(g_V);
    __nv_bfloat16* p_qnh = SYMB(g_qnh);   __nv_bfloat16* p_qnl = SYMB(g_qnl);
    __nv_bfloat16* p_kvnh = SYMB(g_kvnh); __nv_bfloat16* p_kvnl = SYMB(g_kvnl);
    __nv_bfloat16* p_Wqh = SYMB(g_Wqh);   __nv_bfloat16* p_Wql = SYMB(g_Wql);
    __nv_bfloat16* p_Wkh = SYMB(g_Wkh);   __nv_bfloat16* p_Wkl = SYMB(g_Wkl);
    __nv_bfloat16* p_Wvh = SYMB(g_Wvh);   __nv_bfloat16* p_Wvl = SYMB(g_Wvl);
    __nv_bfloat16* p_Woh = SYMB(g_Woh);   __nv_bfloat16* p_Wol = SYMB(g_Wol);
    __nv_bfloat16* p_ctxh = SYMB(g_ctxh); __nv_bfloat16* p_ctxl = SYMB(g_ctxl);
    __nv_bfloat16* p_Qh = SYMB(g_Qh);     __nv_bfloat16* p_Ql = SYMB(g_Ql);
    __nv_bfloat16* p_Kh = SYMB(g_Kh);     __nv_bfloat16* p_Kl = SYMB(g_Kl);

    cudaFuncSetAttribute(gemm_mma, cudaFuncAttributeMaxDynamicSharedMemorySize, GS_TOTAL);
    cudaFuncSetAttribute(qk_mma, cudaFuncAttributeMaxDynamicSharedMemorySize, 65536);
    cudaFuncSetAttribute(av_mma, cudaFuncAttributeMaxDynamicSharedMemorySize, 49152);

    // side stream for the V pipeline + Wo conversion (off the qk/rpe/softmax critical path)
    cudaStream_t s2;
    cudaStreamCreate(&s2);
    cudaEvent_t evFork, evJoin;
    cudaEventCreateWithFlags(&evFork, cudaEventDisableTiming);
    cudaEventCreateWithFlags(&evJoin, cudaEventDisableTiming);

    dim3 wt(32, 8);
    dim3 wg(32, 32);

    // main chain
    mask_kernel<<<1, 256>>>(mask);
    ln_kernel<<<BB * NQ + BB * NKV, 256>>>(q, kv, lg, lb);
    cudaEventRecord(evFork, 0);

    wconv_kernel<<<wg, wt>>>(Wq, p_Wqh, p_Wql);
    wconv_kernel<<<wg, wt>>>(Wk, p_Wkh, p_Wkl);
    gemm_mma<<<dim3(8, 16), 256, GS_TOTAL>>>(p_qnh, p_qnl, p_Wqh, p_Wql, bq, nullptr, p_Qh, p_Ql);
    gemm_mma<<<dim3(8, 32), 256, GS_TOTAL>>>(p_kvnh, p_kvnl, p_Wkh, p_Wkl, bk, nullptr, p_Kh, p_Kl);
    qk_mma<<<dim3(NKV / 128, NQ / 128, BB * NH), 256, 65536>>>(attn);
    rpe_mma<<<dim3(NKV / 128, NQ), 128>>>(rpe, attn);
    softmax_kernel<<<BB * NH * NQ, 256>>>(attn);

    // side chain: V projection + transpose/split + Wo conversion
    cudaStreamWaitEvent(s2, evFork, 0);
    wconv_kernel<<<wg, wt, 0, s2>>>(Wv, p_Wvh, p_Wvl);
    gemm_mma<<<dim3(8, 32), 256, GS_TOTAL, s2>>>(p_kvnh, p_kvnl, p_Wvh, p_Wvl, bv, p_V, nullptr, nullptr);
    vconv_kernel<<<dim3(NKV / 32, 2, BB * NH), wt, 0, s2>>>();
    wconv_kernel<<<wg, wt, 0, s2>>>(Wo, p_Woh, p_Wol);
    cudaEventRecord(evJoin, s2);

    // join: av needs softmax (main) + vconv (s2); final gemm needs Wo conv (s2)
    cudaStreamWaitEvent(0, evJoin, 0);
    av_mma<<<dim3(NQ / 128, BB * NH), 256, 49152>>>(attn);
    gemm_mma<<<dim3(8, 16), 256, GS_TOTAL>>>(p_ctxh, p_ctxl, p_Woh, p_Wol, bo, out, nullptr, nullptr);
}

// round 16
// speedup vs baseline: 1.4961x; 1.0398x over previous
#include <cuda_runtime.h>
#include <cuda_bf16.h>
#include <cstdint>
#include <math.h>

#define BB 2
#define NQ 1024
#define NKV 2048
#define DM 1024
#define NH 16
#define DH 64
#define SCALE 0.125f
#define LNEPS 1e-5f

// ================= scratch (alloc-free rule: __device__ globals) ================
__device__ __nv_bfloat16 g_qnh[BB * NQ * DM], g_qnl[BB * NQ * DM];
__device__ __nv_bfloat16 g_kvnh[BB * NKV * DM], g_kvnl[BB * NKV * DM];
__device__ __nv_bfloat16 g_Wqh[DM * DM], g_Wql[DM * DM];
__device__ __nv_bfloat16 g_Wkh[DM * DM], g_Wkl[DM * DM];
__device__ __nv_bfloat16 g_Wvh[DM * DM], g_Wvl[DM * DM];
__device__ __nv_bfloat16 g_Woh[DM * DM], g_Wol[DM * DM];
__device__ __nv_bfloat16 g_ctxh[BB * NQ * NH * DH], g_ctxl[BB * NQ * NH * DH];
__device__ __nv_bfloat16 g_Qh[BB * NQ * DM], g_Ql[BB * NQ * DM];
__device__ __nv_bfloat16 g_Kh[BB * NKV * DM], g_Kl[BB * NKV * DM];
__device__ __nv_bfloat16 g_Vth[BB * NH * DH * NKV], g_Vtl[BB * NH * DH * NKV]; // [bh][d][kv]
__device__ float g_V[BB * NKV * NH * DH];
__device__ float g_mask[BB * NKV];
__device__ float g_attn_fallback[(size_t)BB * NH * NQ * NKV];

__device__ __forceinline__ void split_bf16(float x, __nv_bfloat16& h, __nv_bfloat16& l) {
    h = __float2bfloat16_rn(x);
    l = __float2bfloat16_rn(x - __bfloat162float(h));
}
__device__ __forceinline__ uint32_t smem_u32(const void* p) {
    uint32_t a;
    asm("{ .reg .u64 t; cvta.to.shared.u64 t, %1; cvt.u32.u64 %0, t; }" : "=r"(a) : "l"(p));
    return a;
}
__device__ __forceinline__ void ldsm4(uint32_t* d, uint32_t addr) {
    asm volatile("ldmatrix.sync.aligned.m8n8.x4.shared.b16 {%0,%1,%2,%3}, [%4];"
                 : "=r"(d[0]), "=r"(d[1]), "=r"(d[2]), "=r"(d[3]) : "r"(addr));
}
__device__ __forceinline__ void mma16816(float* c, const uint32_t* a, uint32_t b0, uint32_t b1) {
    asm volatile("mma.sync.aligned.m16n8k16.row.col.f32.bf16.bf16.f32 "
                 "{%0,%1,%2,%3}, {%4,%5,%6,%7}, {%8,%9}, {%0,%1,%2,%3};"
                 : "+f"(c[0]), "+f"(c[1]), "+f"(c[2]), "+f"(c[3])
                 : "r"(a[0]), "r"(a[1]), "r"(a[2]), "r"(a[3]), "r"(b0), "r"(b1));
}
#define CP_A16(dst, src) \
    asm volatile("cp.async.cg.shared.global [%0], [%1], 16;" :: "r"(dst), "l"(src) : "memory")
#define CP_COMMIT() asm volatile("cp.async.commit_group;" ::: "memory")
#define CP_WAIT1() asm volatile("cp.async.wait_group 1;" ::: "memory")
#define CP_WAIT0() asm volatile("cp.async.wait_group 0;" ::: "memory")

// ---------------- mask normalization: dtype-agnostic ------
__global__ void mask_kernel(const unsigned char* __restrict__ m) {
    __shared__ int s_ge2, s_off;
    int t = threadIdx.x;
    if (t == 0) { s_ge2 = 0; s_off = 0; }
    __syncthreads();
    int ge2 = 0, off = 0;
    for (int i = t; i < BB * NKV; i += 256) {
        unsigned char b = m[i];
        if (b >= 2) ge2 = 1;
        if ((i & 3) && b) off = 1;
    }
    if (ge2) atomicOr(&s_ge2, 1);
    if (off) atomicOr(&s_off, 1);
    __syncthreads();
    int kind = s_ge2 ? 2 : (s_off ? 0 : 1);
    for (int i = t; i < BB * NKV; i += 256) {
        float v;
        if (kind == 2)      v = (((const float*)m)[i] != 0.0f) ? 1.0f : 0.0f;
        else if (kind == 1) v = (((const int*)m)[i] != 0) ? 1.0f : 0.0f;
        else                v = (m[i] != 0) ? 1.0f : 0.0f;
        g_mask[i] = v;
    }
}

// ---------------- LayerNorm -> bf16 hi/lo ----------------
__global__ void ln_kernel(const float* __restrict__ q, const float* __restrict__ kv,
                          const float* __restrict__ gam, const float* __restrict__ bet) {
    __shared__ float red[256];
    int row = blockIdx.x;
    const float* src;
    __nv_bfloat16 *dh, *dl;
    if (row < BB * NQ) {
        src = q + (size_t)row * DM;
        dh = g_qnh + (size_t)row * DM; dl = g_qnl + (size_t)row * DM;
    } else {
        int r = row - BB * NQ;
        src = kv + (size_t)r * DM;
        dh = g_kvnh + (size_t)r * DM; dl = g_kvnl + (size_t)r * DM;
    }
    int t = threadIdx.x;
    float4 x = ((const float4*)src)[t];
    red[t] = x.x + x.y + x.z + x.w;
    __syncthreads();
    for (int o = 128; o > 0; o >>= 1) { if (t < o) red[t] += red[t + o]; __syncthreads(); }
    float mu = red[0] * (1.0f / DM);
    __syncthreads();
    float dx = x.x - mu, dy = x.y - mu, dz = x.z - mu, dw = x.w - mu;
    red[t] = dx * dx + dy * dy + dz * dz + dw * dw;
    __syncthreads();
    for (int o = 128; o > 0; o >>= 1) { if (t < o) red[t] += red[t + o]; __syncthreads(); }
    float rstd = rsqrtf(red[0] * (1.0f / DM) + LNEPS);
    float4 g4 = ((const float4*)gam)[t];
    float4 b4 = ((const float4*)bet)[t];
    float o0 = dx * rstd * g4.x + b4.x;
    float o1 = dy * rstd * g4.y + b4.y;
    float o2 = dz * rstd * g4.z + b4.z;
    float o3 = dw * rstd * g4.w + b4.w;
    __nv_bfloat16 h[4], l[4];
    split_bf16(o0, h[0], l[0]); split_bf16(o1, h[1], l[1]);
    split_bf16(o2, h[2], l[2]); split_bf16(o3, h[3], l[3]);
    *(uint2*)(dh + 4 * t) = *(uint2*)h;
    *(uint2*)(dl + 4 * t) = *(uint2*)l;
}

// ---------------- weight transpose + bf16 split ----------------
__global__ void wconv_kernel(const float* __restrict__ W,
                             __nv_bfloat16* __restrict__ Th, __nv_bfloat16* __restrict__ Tl) {
    __shared__ float tile[32][33];
    int bx = blockIdx.x * 32;  // n
    int by = blockIdx.y * 32;  // k
    int tx = threadIdx.x, ty = threadIdx.y;
#pragma unroll
    for (int i = 0; i < 32; i += 8)
        tile[ty + i][tx] = W[(size_t)(by + ty + i) * DM + bx + tx];
    __syncthreads();
#pragma unroll
    for (int i = 0; i < 32; i += 8) {
        float v = tile[tx][ty + i];
        __nv_bfloat16 h, l;
        split_bf16(v, h, l);
        Th[(size_t)(bx + ty + i) * DM + by + tx] = h;
        Tl[(size_t)(bx + ty + i) * DM + by + tx] = l;
    }
}

// ---------------- V fp32 [b,kv,h,d] -> transposed split [bh][d][kv] bf16 --------
__global__ void vconv_kernel() {
    __shared__ float tile[32][33];
    int bh = blockIdx.z;
    int b = bh >> 4, h = bh & 15;
    int kv0 = blockIdx.x * 32, d0 = blockIdx.y * 32;
    int tx = threadIdx.x, ty = threadIdx.y;
#pragma unroll
    for (int i = 0; i < 32; i += 8)
        tile[ty + i][tx] = g_V[(size_t)(b * NKV + kv0 + ty + i) * DM + h * DH + d0 + tx];
    __syncthreads();
#pragma unroll
    for (int i = 0; i < 32; i += 8) {
        float v = tile[tx][ty + i];
        __nv_bfloat16 h2, l2;
        split_bf16(v, h2, l2);
        size_t o = ((size_t)bh * DH + d0 + ty + i) * NKV + kv0 + tx;
        g_Vth[o] = h2; g_Vtl[o] = l2;
    }
}

// ==== HMMA GEMM, cp.async double-buffered: C[M,1024] = (Ah+Al)@(Bh+Bl)^T + bias ===
// K-chunk 32; per stage: 4 tiles of 128x32 bf16 (8KB each) = 32KB; 2 stages = 64KB.
// Row stride 64B, swizzle: chunk c ^= (r>>1)&3 -> conflict-free ldmatrix.
#define TST_SZ 32768
#define TA_H 0
#define TA_L 8192
#define TB_H 16384
#define TB_L 24576
#define GS_TOTAL 65536

__global__ __launch_bounds__(256, 2) void gemm_mma(
    const __nv_bfloat16* __restrict__ Ah, const __nv_bfloat16* __restrict__ Al,
    const __nv_bfloat16* __restrict__ Bh, const __nv_bfloat16* __restrict__ Bl,
    const float* __restrict__ bias, float* __restrict__ C,
    __nv_bfloat16* __restrict__ Ch, __nv_bfloat16* __restrict__ Cl) {
    extern __shared__ char smem[];
    uint32_t sb = smem_u32(smem);
    int t = threadIdx.x, lane = t & 31, wid = t >> 5;
    int wm = wid & 1, wn = wid >> 1;
    int m0 = blockIdx.y * 128, n0 = blockIdx.x * 128;

    float acc[4][4][4];
#pragma unroll
    for (int i = 0; i < 4; i++)
#pragma unroll
        for (int j = 0; j < 4; j++)
#pragma unroll
            for (int k = 0; k < 4; k++) acc[i][j][k] = 0.0f;

    // issue cp.async loads for k-chunk kt into stage kt&1
    auto issue = [&](int kt) {
        uint32_t base = sb + (uint32_t)(kt & 1) * TST_SZ;
        int kg = kt * 32;
#pragma unroll
        for (int i = 0; i < 2; i++) {
            int id = i * 256 + t;          // 512 chunks of 16B per tile
            int r = id >> 2, c = id & 3;
            uint32_t off = (uint32_t)(r * 64 + (((c ^ ((r >> 1) & 3))) << 4));
            size_t ga = (size_t)(m0 + r) * DM + kg + c * 8;
            size_t gb = (size_t)(n0 + r) * DM + kg + c * 8;
            CP_A16(base + TA_H + off, Ah + ga);
            CP_A16(base + TA_L + off, Al + ga);
            CP_A16(base + TB_H + off, Bh + gb);
            CP_A16(base + TB_L + off, Bl + gb);
        }
    };

    issue(0);
    CP_COMMIT();
    for (int kt = 0; kt < 32; kt++) {
        if (kt + 1 < 32) { issue(kt + 1); CP_COMMIT(); CP_WAIT1(); }
        else CP_WAIT0();
        __syncthreads();
        uint32_t base = sb + (uint32_t)(kt & 1) * TST_SZ;
#pragma unroll
        for (int ks = 0; ks < 2; ks++) {
            uint32_t bh2[2][4], bl2[2][4];
#pragma unroll
            for (int j = 0; j < 2; j++) {
                int rowb = wn * 32 + j * 16 + (lane & 15);
                int ch = ks * 2 + (lane >> 4);
                uint32_t so = (uint32_t)(rowb * 64 + ((ch ^ ((rowb >> 1) & 3)) << 4));
                ldsm4(bh2[j], base + TB_H + so);
                ldsm4(bl2[j], base + TB_L + so);
            }
#pragma unroll
            for (int mi = 0; mi < 4; mi++) {
                int rowa = wm * 64 + mi * 16 + (lane & 15);
                int ch = ks * 2 + (lane >> 4);
                uint32_t so = (uint32_t)(rowa * 64 + ((ch ^ ((rowa >> 1) & 3)) << 4));
                uint32_t ah[4], al[4];
                ldsm4(ah, base + TA_H + so);
                ldsm4(al, base + TA_L + so);
#pragma unroll
                for (int ni = 0; ni < 4; ni++) {
                    int j = ni >> 1, s = ni & 1;
                    mma16816(acc[mi][ni], ah, bh2[j][s], bh2[j][s + 2]);
                    mma16816(acc[mi][ni], ah, bl2[j][s], bl2[j][s + 2]);
                    mma16816(acc[mi][ni], al, bh2[j][s], bh2[j][s + 2]);
                }
            }
        }
        __syncthreads();
    }

#pragma unroll
    for (int mi = 0; mi < 4; mi++) {
#pragma unroll
        for (int ni = 0; ni < 4; ni++) {
            int m = m0 + wm * 64 + mi * 16 + (lane >> 2);
            int n = n0 + wn * 32 + ni * 8 + (lane & 3) * 2;
            float2 bv = *(const float2*)(bias + n);
            float2 v0 = make_float2(acc[mi][ni][0] + bv.x, acc[mi][ni][1] + bv.y);
            float2 v1 = make_float2(acc[mi][ni][2] + bv.x, acc[mi][ni][3] + bv.y);
            if (C) {
                *(float2*)(C + (size_t)m * DM + n) = v0;
                *(float2*)(C + (size_t)(m + 8) * DM + n) = v1;
            }
            if (Ch) {
                __nv_bfloat16 h0, l0, h1, l1;
                split_bf16(v0.x, h0, l0); split_bf16(v0.y, h1, l1);
                *(__nv_bfloat162*)(Ch + (size_t)m * DM + n) = __nv_bfloat162(h0, h1);
                *(__nv_bfloat162*)(Cl + (size_t)m * DM + n) = __nv_bfloat162(l0, l1);
                split_bf16(v1.x, h0, l0); split_bf16(v1.y, h1, l1);
                *(__nv_bfloat162*)(Ch + (size_t)(m + 8) * DM + n) = __nv_bfloat162(h0, h1);
                *(__nv_bfloat162*)(Cl + (size_t)(m + 8) * DM + n) = __nv_bfloat162(l0, l1);
            }
        }
    }
}

// ================= qk HMMA: attn[bh][q][k] = mask ? (Q.K)*SCALE : -inf =========
__global__ __launch_bounds__(256, 2) void qk_mma(float* __restrict__ attn) {
    extern __shared__ char smem[];
    uint32_t sb = smem_u32(smem);
    const int SA_H = 0, SA_L = 16384, SB_H = 32768, SB_L = 49152;
    int t = threadIdx.x, lane = t & 31, wid = t >> 5;
    int wm = wid & 1, wn = wid >> 1;
    int bhead = blockIdx.z;
    int b = bhead >> 4, h = bhead & 15;
    int q0 = blockIdx.y * 128, k0 = blockIdx.x * 128;

#pragma unroll
    for (int i = 0; i < 4; i++) {
        int id = i * 256 + t;
        int r = id >> 3, c8 = id & 7;
        uint32_t off = (uint32_t)(r * 128 + ((c8 ^ (r & 7)) << 4));
        size_t qa = (size_t)(b * NQ + q0 + r) * DM + h * DH + c8 * 8;
        size_t ka = (size_t)(b * NKV + k0 + r) * DM + h * DH + c8 * 8;
        *(uint4*)(smem + SA_H + off) = *(const uint4*)(g_Qh + qa);
        *(uint4*)(smem + SA_L + off) = *(const uint4*)(g_Ql + qa);
        *(uint4*)(smem + SB_H + off) = *(const uint4*)(g_Kh + ka);
        *(uint4*)(smem + SB_L + off) = *(const uint4*)(g_Kl + ka);
    }
    __syncthreads();

    float acc[4][4][4];
#pragma unroll
    for (int i = 0; i < 4; i++)
#pragma unroll
        for (int j = 0; j < 4; j++)
#pragma unroll
            for (int k = 0; k < 4; k++) acc[i][j][k] = 0.0f;

#pragma unroll
    for (int ks = 0; ks < 4; ks++) {
        int c0 = ks * 2;
        uint32_t bh2[2][4], bl2[2][4];
#pragma unroll
        for (int j = 0; j < 2; j++) {
            int rowb = wn * 32 + j * 16 + (lane & 15);
            int ch = c0 + (lane >> 4);
            uint32_t so = (uint32_t)(rowb * 128 + ((ch ^ (rowb & 7)) << 4));
            ldsm4(bh2[j], sb + SB_H + so);
            ldsm4(bl2[j], sb + SB_L + so);
        }
#pragma unroll
        for (int mi = 0; mi < 4; mi++) {
            int rowa = wm * 64 + mi * 16 + (lane & 15);
            int ch = c0 + (lane >> 4);
            uint32_t so = (uint32_t)(rowa * 128 + ((ch ^ (rowa & 7)) << 4));
            uint32_t ah[4], al[4];
            ldsm4(ah, sb + SA_H + so);
            ldsm4(al, sb + SA_L + so);
#pragma unroll
            for (int ni = 0; ni < 4; ni++) {
                int j = ni >> 1, s = ni & 1;
                mma16816(acc[mi][ni], ah, bh2[j][s], bh2[j][s + 2]);
                mma16816(acc[mi][ni], ah, bl2[j][s], bl2[j][s + 2]);
                mma16816(acc[mi][ni], al, bh2[j][s], bh2[j][s + 2]);
            }
        }
    }

#pragma unroll
    for (int mi = 0; mi < 4; mi++) {
#pragma unroll
        for (int ni = 0; ni < 4; ni++) {
            int m = q0 + wm * 64 + mi * 16 + (lane >> 2);
            int n = k0 + wn * 32 + ni * 8 + (lane & 3) * 2;
            float m0v = g_mask[b * NKV + n], m1v = g_mask[b * NKV + n + 1];
            float2 v0, v1;
            v0.x = m0v != 0.0f ? acc[mi][ni][0] * SCALE : -INFINITY;
            v0.y = m1v != 0.0f ? acc[mi][ni][1] * SCALE : -INFINITY;
            v1.x = m0v != 0.0f ? acc[mi][ni][2] * SCALE : -INFINITY;
            v1.y = m1v != 0.0f ? acc[mi][ni][3] * SCALE : -INFINITY;
            *(float2*)(attn + ((size_t)bhead * NQ + m) * NKV + n) = v0;
            *(float2*)(attn + ((size_t)bhead * NQ + m + 8) * NKV + n) = v1;
        }
    }
}

// ================= rpe HMMA: attn[bh][q][k] += SCALE * Qh . rpe_bf16 ===========
__global__ __launch_bounds__(128) void rpe_mma(const float* __restrict__ rpe,
                                               float* __restrict__ attn) {
    __shared__ __nv_bfloat16 Rp[128 * 64];   // [k][d] swizzled, 16KB
    __shared__ __nv_bfloat16 Qs[32 * 64];    // [bh][d] swizzled, 4KB
    uint32_t sRp = smem_u32(Rp), sQs = smem_u32(Qs);
    int t = threadIdx.x, lane = t & 31, w = t >> 5;
    int q = blockIdx.y;
    int k0 = blockIdx.x * 128;

    const float4* gr = (const float4*)(rpe + ((size_t)q * NKV + k0) * DH);
#pragma unroll
    for (int i = 0; i < 16; i++) {
        int idx = i * 128 + t;
        int r = idx >> 4, c4 = idx & 15;
        float4 v = gr[idx];
        __nv_bfloat16 bv[4] = {__float2bfloat16_rn(v.x), __float2bfloat16_rn(v.y),
                               __float2bfloat16_rn(v.z), __float2bfloat16_rn(v.w)};
        int c8 = c4 >> 1, half = c4 & 1;
        *(uint2*)((char*)Rp + r * 128 + ((c8 ^ (r & 7)) << 4) + half * 8) = *(uint2*)bv;
    }
#pragma unroll
    for (int i = 0; i < 2; i++) {
        int id = i * 128 + t;
        int r = id >> 3, c8 = id & 7;
        int b = r >> 4, h = r & 15;
        *(uint4*)((char*)Qs + r * 128 + ((c8 ^ (r & 7)) << 4)) =
            *(const uint4*)(g_Qh + (size_t)(b * NQ + q) * DM + h * DH + c8 * 8);
    }
    __syncthreads();

    float acc[2][4][4];
#pragma unroll
    for (int i = 0; i < 2; i++)
#pragma unroll
        for (int j = 0; j < 4; j++)
#pragma unroll
            for (int k = 0; k < 4; k++) acc[i][j][k] = 0.0f;

#pragma unroll
    for (int ks = 0; ks < 4; ks++) {
        int c0 = ks * 2;
        uint32_t bf[2][4];
#pragma unroll
        for (int j = 0; j < 2; j++) {
            int rowb = w * 32 + j * 16 + (lane & 15);
            int ch = c0 + (lane >> 4);
            ldsm4(bf[j], sRp + (uint32_t)(rowb * 128 + ((ch ^ (rowb & 7)) << 4)));
        }
#pragma unroll
        for (int mi = 0; mi < 2; mi++) {
            int rowa = mi * 16 + (lane & 15);
            int ch = c0 + (lane >> 4);
            uint32_t af[4];
            ldsm4(af, sQs + (uint32_t)(rowa * 128 + ((ch ^ (rowa & 7)) << 4)));
#pragma unroll
            for (int ni = 0; ni < 4; ni++) {
                int j = ni >> 1, s = ni & 1;
                mma16816(acc[mi][ni], af, bf[j][s], bf[j][s + 2]);
            }
        }
    }

#pragma unroll
    for (int mi = 0; mi < 2; mi++) {
#pragma unroll
        for (int ni = 0; ni < 4; ni++) {
            int m = mi * 16 + (lane >> 2);           // bh
            int n = k0 + w * 32 + ni * 8 + (lane & 3) * 2;
            float* p0 = attn + ((size_t)m * NQ + q) * NKV + n;
            float* p1 = attn + ((size_t)(m + 8) * NQ + q) * NKV + n;
            float2 c0v = *(float2*)p0, c1v = *(float2*)p1;
            c0v.x += SCALE * acc[mi][ni][0]; c0v.y += SCALE * acc[mi][ni][1];
            c1v.x += SCALE * acc[mi][ni][2]; c1v.y += SCALE * acc[mi][ni][3];
            *(float2*)p0 = c0v;
            *(float2*)p1 = c1v;
        }
    }
}

// ---------------- softmax (in place, warp-shuffle reductions) ----------------
__global__ void softmax_kernel(float* __restrict__ attn) {
    __shared__ float wm[8], ws[8];
    size_t row = blockIdx.x;
    float4* p = (float4*)(attn + row * (size_t)NKV);
    int t = threadIdx.x, lane = t & 31, w = t >> 5;
    float4 v1 = p[t], v2 = p[t + 256];
    float m = fmaxf(fmaxf(fmaxf(v1.x, v1.y), fmaxf(v1.z, v1.w)),
                    fmaxf(fmaxf(v2.x, v2.y), fmaxf(v2.z, v2.w)));
#pragma unroll
    for (int o = 16; o > 0; o >>= 1) m = fmaxf(m, __shfl_xor_sync(0xffffffffu, m, o));
    if (lane == 0) wm[w] = m;
    __syncthreads();
    float M = fmaxf(fmaxf(fmaxf(wm[0], wm[1]), fmaxf(wm[2], wm[3])),
                    fmaxf(fmaxf(wm[4], wm[5]), fmaxf(wm[6], wm[7])));
    v1.x = __expf(v1.x - M); v1.y = __expf(v1.y - M); v1.z = __expf(v1.z - M); v1.w = __expf(v1.w - M);
    v2.x = __expf(v2.x - M); v2.y = __expf(v2.y - M); v2.z = __expf(v2.z - M); v2.w = __expf(v2.w - M);
    float s = v1.x + v1.y + v1.z + v1.w + v2.x + v2.y + v2.z + v2.w;
#pragma unroll
    for (int o = 16; o > 0; o >>= 1) s += __shfl_xor_sync(0xffffffffu, s, o);
    if (lane == 0) ws[w] = s;
    __syncthreads();
    float inv = 1.0f / (ws[0] + ws[1] + ws[2] + ws[3] + ws[4] + ws[5] + ws[6] + ws[7]);
    v1.x *= inv; v1.y *= inv; v1.z *= inv; v1.w *= inv;
    v2.x *= inv; v2.y *= inv; v2.z *= inv; v2.w *= inv;
    p[t] = v1;
    p[t + 256] = v2;
}

// == av HMMA: read fp32 probs, split hi/lo in smem fill; ctx -> bf16 hi/lo ======
__global__ __launch_bounds__(256, 2) void av_mma(const float* __restrict__ attn) {
    extern __shared__ char smem[];
    uint32_t sb = smem_u32(smem);
    const int SA_H = 0, SA_L = 16384, SB_H = 32768, SB_L = 40960;
    int t = threadIdx.x, lane = t & 31, wid = t >> 5;
    int wm = wid >> 1, wn = wid & 1;
    int bhead = blockIdx.y;
    int b = bhead >> 4, h = bhead & 15;
    int q0 = blockIdx.x * 128;

    float acc[2][4][4];
#pragma unroll
    for (int i = 0; i < 2; i++)
#pragma unroll
        for (int j = 0; j < 4; j++)
#pragma unroll
            for (int k = 0; k < 4; k++) acc[i][j][k] = 0.0f;

    for (int kt = 0; kt < 32; kt++) {
        int kg = kt * 64;
        if (kt > 0) __syncthreads();
#pragma unroll
        for (int i = 0; i < 8; i++) {
            int idx = i * 256 + t;
            int r = idx >> 4, c4 = idx & 15;
            float4 v = *(const float4*)(attn + ((size_t)bhead * NQ + q0 + r) * NKV + kg + c4 * 4);
            __nv_bfloat16 hh[4], ll[4];
            split_bf16(v.x, hh[0], ll[0]); split_bf16(v.y, hh[1], ll[1]);
            split_bf16(v.z, hh[2], ll[2]); split_bf16(v.w, hh[3], ll[3]);
            int c8 = c4 >> 1, half = c4 & 1;
            uint32_t off = (uint32_t)(r * 128 + ((c8 ^ (r & 7)) << 4) + half * 8);
            *(uint2*)(smem + SA_H + off) = *(uint2*)hh;
            *(uint2*)(smem + SA_L + off) = *(uint2*)ll;
        }
#pragma unroll
        for (int i = 0; i < 2; i++) {
            int id2 = i * 256 + t;
            int r = id2 >> 3, c8 = id2 & 7;
            uint32_t off = (uint32_t)(r * 128 + ((c8 ^ (r & 7)) << 4));
            size_t gv = ((size_t)bhead * DH + r) * NKV + kg + c8 * 8;
            *(uint4*)(smem + SB_H + off) = *(const uint4*)(g_Vth + gv);
            *(uint4*)(smem + SB_L + off) = *(const uint4*)(g_Vtl + gv);
        }
        __syncthreads();
#pragma unroll
        for (int ks = 0; ks < 4; ks++) {
            int c0 = ks * 2;
            uint32_t bh2[2][4], bl2[2][4];
#pragma unroll
            for (int j = 0; j < 2; j++) {
                int rowb = wn * 32 + j * 16 + (lane & 15);
                int ch = c0 + (lane >> 4);
                uint32_t so = (uint32_t)(rowb * 128 + ((ch ^ (rowb & 7)) << 4));
                ldsm4(bh2[j], sb + SB_H + so);
                ldsm4(bl2[j], sb + SB_L + so);
            }
#pragma unroll
            for (int mi = 0; mi < 2; mi++) {
                int rowa = wm * 32 + mi * 16 + (lane & 15);
                int ch = c0 + (lane >> 4);
                uint32_t so = (uint32_t)(rowa * 128 + ((ch ^ (rowa & 7)) << 4));
                uint32_t ah[4], al[4];
                ldsm4(ah, sb + SA_H + so);
                ldsm4(al, sb + SA_L + so);
#pragma unroll
                for (int ni = 0; ni < 4; ni++) {
                    int j = ni >> 1, s = ni & 1;
                    mma16816(acc[mi][ni], ah, bh2[j][s], bh2[j][s + 2]);
                    mma16816(acc[mi][ni], ah, bl2[j][s], bl2[j][s + 2]);
                    mma16816(acc[mi][ni], al, bh2[j][s], bh2[j][s + 2]);
                }
            }
        }
    }

#pragma unroll
    for (int mi = 0; mi < 2; mi++) {
#pragma unroll
        for (int ni = 0; ni < 4; ni++) {
            int m = q0 + wm * 32 + mi * 16 + (lane >> 2);
            int n = wn * 32 + ni * 8 + (lane & 3) * 2;
            __nv_bfloat16 h0, l0, h1, l1;
            split_bf16(acc[mi][ni][0], h0, l0); split_bf16(acc[mi][ni][1], h1, l1);
            *(__nv_bfloat162*)(g_ctxh + (size_t)(b * NQ + m) * DM + h * DH + n) = __nv_bfloat162(h0, h1);
            *(__nv_bfloat162*)(g_ctxl + (size_t)(b * NQ + m) * DM + h * DH + n) = __nv_bfloat162(l0, l1);
            split_bf16(acc[mi][ni][2], h0, l0); split_bf16(acc[mi][ni][3], h1, l1);
            *(__nv_bfloat162*)(g_ctxh + (size_t)(b * NQ + m + 8) * DM + h * DH + n) = __nv_bfloat162(h0, h1);
            *(__nv_bfloat162*)(g_ctxl + (size_t)(b * NQ + m + 8) * DM + h * DH + n) = __nv_bfloat162(l0, l1);
        }
    }
}

// ---------------- launch ----------------
extern "C" void kernel_launch(void* const* d_in, const int* in_sizes, int n_in,
                              void* d_out, int out_size) {
    const float* q = (const float*)d_in[0];
    const float* kv = (const float*)d_in[1];
    const unsigned char* mask = (const unsigned char*)d_in[2];
    const float* rpe = (const float*)d_in[3];
    const float* Wq = (const float*)d_in[4];
    const float* bq = (const float*)d_in[5];
    const float* Wk = (const float*)d_in[6];
    const float* bk = (const float*)d_in[7];
    const float* Wv = (const float*)d_in[8];
    const float* bv = (const float*)d_in[9];
    const float* Wo = (const float*)d_in[10];
    const float* bo = (const float*)d_in[11];
    const float* lg = (const float*)d_in[12];
    const float* lb = (const float*)d_in[13];

    float* out = (float*)d_out;
    const size_t ATT = (size_t)BB * NH * NQ * NKV;
    const size_t OUTN = (size_t)BB * NQ * DM;
    float* attn;
    if ((size_t)out_size >= ATT + OUTN) {
        attn = out + ((size_t)out_size - ATT);
    } else {
        void* p;
        cudaGetSymbolAddress(&p, g_attn_fallback);
        attn = (float*)p;
    }

#define SYMF(sym) ([]{ void* p; cudaGetSymbolAddress(&p, sym); return (float*)p; }())
#define SYMB(sym) ([]{ void* p; cudaGetSymbolAddress(&p, sym); return (__nv_bfloat16*)p; }())
    float* p_V = SYMF(g_V);
    __nv_bfloat16* p_qnh = SYMB(g_qnh);   __nv_bfloat16* p_qnl = SYMB(g_qnl);
    __nv_bfloat16* p_kvnh = SYMB(g_kvnh); __nv_bfloat16* p_kvnl = SYMB(g_kvnl);
    __nv_bfloat16* p_Wqh = SYMB(g_Wqh);   __nv_bfloat16* p_Wql = SYMB(g_Wql);
    __nv_bfloat16* p_Wkh = SYMB(g_Wkh);   __nv_bfloat16* p_Wkl = SYMB(g_Wkl);
    __nv_bfloat16* p_Wvh = SYMB(g_Wvh);   __nv_bfloat16* p_Wvl = SYMB(g_Wvl);
    __nv_bfloat16* p_Woh = SYMB(g_Woh);   __nv_bfloat16* p_Wol = SYMB(g_Wol);
    __nv_bfloat16* p_ctxh = SYMB(g_ctxh); __nv_bfloat16* p_ctxl = SYMB(g_ctxl);
    __nv_bfloat16* p_Qh = SYMB(g_Qh);     __nv_bfloat16* p_Ql = SYMB(g_Ql);
    __nv_bfloat16* p_Kh = SYMB(g_Kh);     __nv_bfloat16* p_Kl = SYMB(g_Kl);

    cudaFuncSetAttribute(gemm_mma, cudaFuncAttributeMaxDynamicSharedMemorySize, GS_TOTAL);
    cudaFuncSetAttribute(qk_mma, cudaFuncAttributeMaxDynamicSharedMemorySize, 65536);
    cudaFuncSetAttribute(av_mma, cudaFuncAttributeMaxDynamicSharedMemorySize, 49152);

    // side stream for the V pipeline + Wo conversion (off the qk/rpe/softmax critical path)
    cudaStream_t s2;
    cudaStreamCreate(&s2);
    cudaEvent_t evFork, evJoin;
    cudaEventCreateWithFlags(&evFork, cudaEventDisableTiming);
    cudaEventCreateWithFlags(&evJoin, cudaEventDisableTiming);

    dim3 wt(32, 8);
    dim3 wg(32, 32);

    // main chain
    mask_kernel<<<1, 256>>>(mask);
    ln_kernel<<<BB * NQ + BB * NKV, 256>>>(q, kv, lg, lb);
    cudaEventRecord(evFork, 0);

    wconv_kernel<<<wg, wt>>>(Wq, p_Wqh, p_Wql);
    wconv_kernel<<<wg, wt>>>(Wk, p_Wkh, p_Wkl);
    gemm_mma<<<dim3(8, 16), 256, GS_TOTAL>>>(p_qnh, p_qnl, p_Wqh, p_Wql, bq, nullptr, p_Qh, p_Ql);
    gemm_mma<<<dim3(8, 32), 256, GS_TOTAL>>>(p_kvnh, p_kvnl, p_Wkh, p_Wkl, bk, nullptr, p_Kh, p_Kl);
    qk_mma<<<dim3(NKV / 128, NQ / 128, BB * NH), 256, 65536>>>(attn);
    rpe_mma<<<dim3(NKV / 128, NQ), 128>>>(rpe, attn);
    softmax_kernel<<<BB * NH * NQ, 256>>>(attn);

    // side chain: V projection + transpose/split + Wo conversion
    cudaStreamWaitEvent(s2, evFork, 0);
    wconv_kernel<<<wg, wt, 0, s2>>>(Wv, p_Wvh, p_Wvl);
    gemm_mma<<<dim3(8, 32), 256, GS_TOTAL, s2>>>(p_kvnh, p_kvnl, p_Wvh, p_Wvl, bv, p_V, nullptr, nullptr);
    vconv_kernel<<<dim3(NKV / 32, 2, BB * NH), wt, 0, s2>>>();
    wconv_kernel<<<wg, wt, 0, s2>>>(Wo, p_Woh, p_Wol);
    cudaEventRecord(evJoin, s2);

    // join: av needs softmax (main) + vconv (s2); final gemm needs Wo conv (s2)
    cudaStreamWaitEvent(0, evJoin, 0);
    av_mma<<<dim3(NQ / 128, BB * NH), 256, 49152>>>(attn);
    gemm_mma<<<dim3(8, 16), 256, GS_TOTAL>>>(p_ctxh, p_ctxl, p_Woh, p_Wol, bo, out, nullptr, nullptr);
}

// round 17
// speedup vs baseline: 1.5008x; 1.0031x over previous
#include <cuda_runtime.h>
#include <cuda_bf16.h>
#include <cstdint>
#include <math.h>

#define BB 2
#define NQ 1024
#define NKV 2048
#define DM 1024
#define NH 16
#define DH 64
#define SCALE 0.125f
#define LNEPS 1e-5f

// ================= scratch (alloc-free rule: __device__ globals) ================
__device__ __nv_bfloat16 g_qnh[BB * NQ * DM], g_qnl[BB * NQ * DM];
__device__ __nv_bfloat16 g_kvnh[BB * NKV * DM], g_kvnl[BB * NKV * DM];
__device__ __nv_bfloat16 g_Wqh[DM * DM], g_Wql[DM * DM];
__device__ __nv_bfloat16 g_Wkh[DM * DM], g_Wkl[DM * DM];
__device__ __nv_bfloat16 g_Wvh[DM * DM], g_Wvl[DM * DM];
__device__ __nv_bfloat16 g_Woh[DM * DM], g_Wol[DM * DM];
__device__ __nv_bfloat16 g_ctxh[BB * NQ * NH * DH], g_ctxl[BB * NQ * NH * DH];
__device__ __nv_bfloat16 g_Qh[BB * NQ * DM], g_Ql[BB * NQ * DM];
__device__ __nv_bfloat16 g_Kh[BB * NKV * DM], g_Kl[BB * NKV * DM];
__device__ __nv_bfloat16 g_Vth[BB * NH * DH * NKV], g_Vtl[BB * NH * DH * NKV]; // [bh][d][kv]
__device__ float g_V[BB * NKV * NH * DH];
__device__ float g_mask[BB * NKV];
__device__ float g_attn_fallback[(size_t)BB * NH * NQ * NKV];

__device__ __forceinline__ void split_bf16(float x, __nv_bfloat16& h, __nv_bfloat16& l) {
    h = __float2bfloat16_rn(x);
    l = __float2bfloat16_rn(x - __bfloat162float(h));
}
__device__ __forceinline__ uint32_t smem_u32(const void* p) {
    uint32_t a;
    asm("{ .reg .u64 t; cvta.to.shared.u64 t, %1; cvt.u32.u64 %0, t; }" : "=r"(a) : "l"(p));
    return a;
}
__device__ __forceinline__ void ldsm4(uint32_t* d, uint32_t addr) {
    asm volatile("ldmatrix.sync.aligned.m8n8.x4.shared.b16 {%0,%1,%2,%3}, [%4];"
                 : "=r"(d[0]), "=r"(d[1]), "=r"(d[2]), "=r"(d[3]) : "r"(addr));
}
__device__ __forceinline__ void mma16816(float* c, const uint32_t* a, uint32_t b0, uint32_t b1) {
    asm volatile("mma.sync.aligned.m16n8k16.row.col.f32.bf16.bf16.f32 "
                 "{%0,%1,%2,%3}, {%4,%5,%6,%7}, {%8,%9}, {%0,%1,%2,%3};"
                 : "+f"(c[0]), "+f"(c[1]), "+f"(c[2]), "+f"(c[3])
                 : "r"(a[0]), "r"(a[1]), "r"(a[2]), "r"(a[3]), "r"(b0), "r"(b1));
}
#define CP_A16(dst, src) \
    asm volatile("cp.async.cg.shared.global [%0], [%1], 16;" :: "r"(dst), "l"(src) : "memory")
#define CP_COMMIT() asm volatile("cp.async.commit_group;" ::: "memory")
#define CP_WAIT1() asm volatile("cp.async.wait_group 1;" ::: "memory")
#define CP_WAIT0() asm volatile("cp.async.wait_group 0;" ::: "memory")

// ---------------- mask normalization: dtype-agnostic ------
__global__ void mask_kernel(const unsigned char* __restrict__ m) {
    __shared__ int s_ge2, s_off;
    int t = threadIdx.x;
    if (t == 0) { s_ge2 = 0; s_off = 0; }
    __syncthreads();
    int ge2 = 0, off = 0;
    for (int i = t; i < BB * NKV; i += 256) {
        unsigned char b = m[i];
        if (b >= 2) ge2 = 1;
        if ((i & 3) && b) off = 1;
    }
    if (ge2) atomicOr(&s_ge2, 1);
    if (off) atomicOr(&s_off, 1);
    __syncthreads();
    int kind = s_ge2 ? 2 : (s_off ? 0 : 1);
    for (int i = t; i < BB * NKV; i += 256) {
        float v;
        if (kind == 2)      v = (((const float*)m)[i] != 0.0f) ? 1.0f : 0.0f;
        else if (kind == 1) v = (((const int*)m)[i] != 0) ? 1.0f : 0.0f;
        else                v = (m[i] != 0) ? 1.0f : 0.0f;
        g_mask[i] = v;
    }
}

// ---------------- LayerNorm -> bf16 hi/lo ----------------
__global__ void ln_kernel(const float* __restrict__ q, const float* __restrict__ kv,
                          const float* __restrict__ gam, const float* __restrict__ bet) {
    __shared__ float red[256];
    int row = blockIdx.x;
    const float* src;
    __nv_bfloat16 *dh, *dl;
    if (row < BB * NQ) {
        src = q + (size_t)row * DM;
        dh = g_qnh + (size_t)row * DM; dl = g_qnl + (size_t)row * DM;
    } else {
        int r = row - BB * NQ;
        src = kv + (size_t)r * DM;
        dh = g_kvnh + (size_t)r * DM; dl = g_kvnl + (size_t)r * DM;
    }
    int t = threadIdx.x;
    float4 x = ((const float4*)src)[t];
    red[t] = x.x + x.y + x.z + x.w;
    __syncthreads();
    for (int o = 128; o > 0; o >>= 1) { if (t < o) red[t] += red[t + o]; __syncthreads(); }
    float mu = red[0] * (1.0f / DM);
    __syncthreads();
    float dx = x.x - mu, dy = x.y - mu, dz = x.z - mu, dw = x.w - mu;
    red[t] = dx * dx + dy * dy + dz * dz + dw * dw;
    __syncthreads();
    for (int o = 128; o > 0; o >>= 1) { if (t < o) red[t] += red[t + o]; __syncthreads(); }
    float rstd = rsqrtf(red[0] * (1.0f / DM) + LNEPS);
    float4 g4 = ((const float4*)gam)[t];
    float4 b4 = ((const float4*)bet)[t];
    float o0 = dx * rstd * g4.x + b4.x;
    float o1 = dy * rstd * g4.y + b4.y;
    float o2 = dz * rstd * g4.z + b4.z;
    float o3 = dw * rstd * g4.w + b4.w;
    __nv_bfloat16 h[4], l[4];
    split_bf16(o0, h[0], l[0]); split_bf16(o1, h[1], l[1]);
    split_bf16(o2, h[2], l[2]); split_bf16(o3, h[3], l[3]);
    *(uint2*)(dh + 4 * t) = *(uint2*)h;
    *(uint2*)(dl + 4 * t) = *(uint2*)l;
}

// ---------------- weight transpose + bf16 split ----------------
__global__ void wconv_kernel(const float* __restrict__ W,
                             __nv_bfloat16* __restrict__ Th, __nv_bfloat16* __restrict__ Tl) {
    __shared__ float tile[32][33];
    int bx = blockIdx.x * 32;  // n
    int by = blockIdx.y * 32;  // k
    int tx = threadIdx.x, ty = threadIdx.y;
#pragma unroll
    for (int i = 0; i < 32; i += 8)
        tile[ty + i][tx] = W[(size_t)(by + ty + i) * DM + bx + tx];
    __syncthreads();
#pragma unroll
    for (int i = 0; i < 32; i += 8) {
        float v = tile[tx][ty + i];
        __nv_bfloat16 h, l;
        split_bf16(v, h, l);
        Th[(size_t)(bx + ty + i) * DM + by + tx] = h;
        Tl[(size_t)(bx + ty + i) * DM + by + tx] = l;
    }
}

// ---------------- V fp32 [b,kv,h,d] -> transposed split [bh][d][kv] bf16 --------
__global__ void vconv_kernel() {
    __shared__ float tile[32][33];
    int bh = blockIdx.z;
    int b = bh >> 4, h = bh & 15;
    int kv0 = blockIdx.x * 32, d0 = blockIdx.y * 32;
    int tx = threadIdx.x, ty = threadIdx.y;
#pragma unroll
    for (int i = 0; i < 32; i += 8)
        tile[ty + i][tx] = g_V[(size_t)(b * NKV + kv0 + ty + i) * DM + h * DH + d0 + tx];
    __syncthreads();
#pragma unroll
    for (int i = 0; i < 32; i += 8) {
        float v = tile[tx][ty + i];
        __nv_bfloat16 h2, l2;
        split_bf16(v, h2, l2);
        size_t o = ((size_t)bh * DH + d0 + ty + i) * NKV + kv0 + tx;
        g_Vth[o] = h2; g_Vtl[o] = l2;
    }
}

// ==== HMMA GEMM, cp.async double-buffered (R16-validated) ====
#define TST_SZ 32768
#define TA_H 0
#define TA_L 8192
#define TB_H 16384
#define TB_L 24576
#define GS_TOTAL 65536

__global__ __launch_bounds__(256, 2) void gemm_mma(
    const __nv_bfloat16* __restrict__ Ah, const __nv_bfloat16* __restrict__ Al,
    const __nv_bfloat16* __restrict__ Bh, const __nv_bfloat16* __restrict__ Bl,
    const float* __restrict__ bias, float* __restrict__ C,
    __nv_bfloat16* __restrict__ Ch, __nv_bfloat16* __restrict__ Cl) {
    extern __shared__ char smem[];
    uint32_t sb = smem_u32(smem);
    int t = threadIdx.x, lane = t & 31, wid = t >> 5;
    int wm = wid & 1, wn = wid >> 1;
    int m0 = blockIdx.y * 128, n0 = blockIdx.x * 128;

    float acc[4][4][4];
#pragma unroll
    for (int i = 0; i < 4; i++)
#pragma unroll
        for (int j = 0; j < 4; j++)
#pragma unroll
            for (int k = 0; k < 4; k++) acc[i][j][k] = 0.0f;

    auto issue = [&](int kt) {
        uint32_t base = sb + (uint32_t)(kt & 1) * TST_SZ;
        int kg = kt * 32;
#pragma unroll
        for (int i = 0; i < 2; i++) {
            int id = i * 256 + t;
            int r = id >> 2, c = id & 3;
            uint32_t off = (uint32_t)(r * 64 + (((c ^ ((r >> 1) & 3))) << 4));
            size_t ga = (size_t)(m0 + r) * DM + kg + c * 8;
            size_t gb = (size_t)(n0 + r) * DM + kg + c * 8;
            CP_A16(base + TA_H + off, Ah + ga);
            CP_A16(base + TA_L + off, Al + ga);
            CP_A16(base + TB_H + off, Bh + gb);
            CP_A16(base + TB_L + off, Bl + gb);
        }
    };

    issue(0);
    CP_COMMIT();
    for (int kt = 0; kt < 32; kt++) {
        if (kt + 1 < 32) { issue(kt + 1); CP_COMMIT(); CP_WAIT1(); }
        else CP_WAIT0();
        __syncthreads();
        uint32_t base = sb + (uint32_t)(kt & 1) * TST_SZ;
#pragma unroll
        for (int ks = 0; ks < 2; ks++) {
            uint32_t bh2[2][4], bl2[2][4];
#pragma unroll
            for (int j = 0; j < 2; j++) {
                int rowb = wn * 32 + j * 16 + (lane & 15);
                int ch = ks * 2 + (lane >> 4);
                uint32_t so = (uint32_t)(rowb * 64 + ((ch ^ ((rowb >> 1) & 3)) << 4));
                ldsm4(bh2[j], base + TB_H + so);
                ldsm4(bl2[j], base + TB_L + so);
            }
#pragma unroll
            for (int mi = 0; mi < 4; mi++) {
                int rowa = wm * 64 + mi * 16 + (lane & 15);
                int ch = ks * 2 + (lane >> 4);
                uint32_t so = (uint32_t)(rowa * 64 + ((ch ^ ((rowa >> 1) & 3)) << 4));
                uint32_t ah[4], al[4];
                ldsm4(ah, base + TA_H + so);
                ldsm4(al, base + TA_L + so);
#pragma unroll
                for (int ni = 0; ni < 4; ni++) {
                    int j = ni >> 1, s = ni & 1;
                    mma16816(acc[mi][ni], ah, bh2[j][s], bh2[j][s + 2]);
                    mma16816(acc[mi][ni], ah, bl2[j][s], bl2[j][s + 2]);
                    mma16816(acc[mi][ni], al, bh2[j][s], bh2[j][s + 2]);
                }
            }
        }
        __syncthreads();
    }

#pragma unroll
    for (int mi = 0; mi < 4; mi++) {
#pragma unroll
        for (int ni = 0; ni < 4; ni++) {
            int m = m0 + wm * 64 + mi * 16 + (lane >> 2);
            int n = n0 + wn * 32 + ni * 8 + (lane & 3) * 2;
            float2 bv = *(const float2*)(bias + n);
            float2 v0 = make_float2(acc[mi][ni][0] + bv.x, acc[mi][ni][1] + bv.y);
            float2 v1 = make_float2(acc[mi][ni][2] + bv.x, acc[mi][ni][3] + bv.y);
            if (C) {
                *(float2*)(C + (size_t)m * DM + n) = v0;
                *(float2*)(C + (size_t)(m + 8) * DM + n) = v1;
            }
            if (Ch) {
                __nv_bfloat16 h0, l0, h1, l1;
                split_bf16(v0.x, h0, l0); split_bf16(v0.y, h1, l1);
                *(__nv_bfloat162*)(Ch + (size_t)m * DM + n) = __nv_bfloat162(h0, h1);
                *(__nv_bfloat162*)(Cl + (size_t)m * DM + n) = __nv_bfloat162(l0, l1);
                split_bf16(v1.x, h0, l0); split_bf16(v1.y, h1, l1);
                *(__nv_bfloat162*)(Ch + (size_t)(m + 8) * DM + n) = __nv_bfloat162(h0, h1);
                *(__nv_bfloat162*)(Cl + (size_t)(m + 8) * DM + n) = __nv_bfloat162(l0, l1);
            }
        }
    }
}

// ================= qk HMMA: attn[bh][q][k] = mask ? (Q.K)*SCALE : -inf =========
__global__ __launch_bounds__(256, 2) void qk_mma(float* __restrict__ attn) {
    extern __shared__ char smem[];
    uint32_t sb = smem_u32(smem);
    const int SA_H = 0, SA_L = 16384, SB_H = 32768, SB_L = 49152;
    int t = threadIdx.x, lane = t & 31, wid = t >> 5;
    int wm = wid & 1, wn = wid >> 1;
    int bhead = blockIdx.z;
    int b = bhead >> 4, h = bhead & 15;
    int q0 = blockIdx.y * 128, k0 = blockIdx.x * 128;

#pragma unroll
    for (int i = 0; i < 4; i++) {
        int id = i * 256 + t;
        int r = id >> 3, c8 = id & 7;
        uint32_t off = (uint32_t)(r * 128 + ((c8 ^ (r & 7)) << 4));
        size_t qa = (size_t)(b * NQ + q0 + r) * DM + h * DH + c8 * 8;
        size_t ka = (size_t)(b * NKV + k0 + r) * DM + h * DH + c8 * 8;
        *(uint4*)(smem + SA_H + off) = *(const uint4*)(g_Qh + qa);
        *(uint4*)(smem + SA_L + off) = *(const uint4*)(g_Ql + qa);
        *(uint4*)(smem + SB_H + off) = *(const uint4*)(g_Kh + ka);
        *(uint4*)(smem + SB_L + off) = *(const uint4*)(g_Kl + ka);
    }
    __syncthreads();

    float acc[4][4][4];
#pragma unroll
    for (int i = 0; i < 4; i++)
#pragma unroll
        for (int j = 0; j < 4; j++)
#pragma unroll
            for (int k = 0; k < 4; k++) acc[i][j][k] = 0.0f;

#pragma unroll
    for (int ks = 0; ks < 4; ks++) {
        int c0 = ks * 2;
        uint32_t bh2[2][4], bl2[2][4];
#pragma unroll
        for (int j = 0; j < 2; j++) {
            int rowb = wn * 32 + j * 16 + (lane & 15);
            int ch = c0 + (lane >> 4);
            uint32_t so = (uint32_t)(rowb * 128 + ((ch ^ (rowb & 7)) << 4));
            ldsm4(bh2[j], sb + SB_H + so);
            ldsm4(bl2[j], sb + SB_L + so);
        }
#pragma unroll
        for (int mi = 0; mi < 4; mi++) {
            int rowa = wm * 64 + mi * 16 + (lane & 15);
            int ch = c0 + (lane >> 4);
            uint32_t so = (uint32_t)(rowa * 128 + ((ch ^ (rowa & 7)) << 4));
            uint32_t ah[4], al[4];
            ldsm4(ah, sb + SA_H + so);
            ldsm4(al, sb + SA_L + so);
#pragma unroll
            for (int ni = 0; ni < 4; ni++) {
                int j = ni >> 1, s = ni & 1;
                mma16816(acc[mi][ni], ah, bh2[j][s], bh2[j][s + 2]);
                mma16816(acc[mi][ni], ah, bl2[j][s], bl2[j][s + 2]);
                mma16816(acc[mi][ni], al, bh2[j][s], bh2[j][s + 2]);
            }
        }
    }

#pragma unroll
    for (int mi = 0; mi < 4; mi++) {
#pragma unroll
        for (int ni = 0; ni < 4; ni++) {
            int m = q0 + wm * 64 + mi * 16 + (lane >> 2);
            int n = k0 + wn * 32 + ni * 8 + (lane & 3) * 2;
            float m0v = g_mask[b * NKV + n], m1v = g_mask[b * NKV + n + 1];
            float2 v0, v1;
            v0.x = m0v != 0.0f ? acc[mi][ni][0] * SCALE : -INFINITY;
            v0.y = m1v != 0.0f ? acc[mi][ni][1] * SCALE : -INFINITY;
            v1.x = m0v != 0.0f ? acc[mi][ni][2] * SCALE : -INFINITY;
            v1.y = m1v != 0.0f ? acc[mi][ni][3] * SCALE : -INFINITY;
            *(float2*)(attn + ((size_t)bhead * NQ + m) * NKV + n) = v0;
            *(float2*)(attn + ((size_t)bhead * NQ + m + 8) * NKV + n) = v1;
        }
    }
}

// ================= rpe HMMA: attn[bh][q][k] += SCALE * Qh . rpe_bf16 ===========
__global__ __launch_bounds__(128) void rpe_mma(const float* __restrict__ rpe,
                                               float* __restrict__ attn) {
    __shared__ __nv_bfloat16 Rp[128 * 64];   // [k][d] swizzled, 16KB
    __shared__ __nv_bfloat16 Qs[32 * 64];    // [bh][d] swizzled, 4KB
    uint32_t sRp = smem_u32(Rp), sQs = smem_u32(Qs);
    int t = threadIdx.x, lane = t & 31, w = t >> 5;
    int q = blockIdx.y;
    int k0 = blockIdx.x * 128;

    const float4* gr = (const float4*)(rpe + ((size_t)q * NKV + k0) * DH);
#pragma unroll
    for (int i = 0; i < 16; i++) {
        int idx = i * 128 + t;
        int r = idx >> 4, c4 = idx & 15;
        float4 v = gr[idx];
        __nv_bfloat16 bv[4] = {__float2bfloat16_rn(v.x), __float2bfloat16_rn(v.y),
                               __float2bfloat16_rn(v.z), __float2bfloat16_rn(v.w)};
        int c8 = c4 >> 1, half = c4 & 1;
        *(uint2*)((char*)Rp + r * 128 + ((c8 ^ (r & 7)) << 4) + half * 8) = *(uint2*)bv;
    }
#pragma unroll
    for (int i = 0; i < 2; i++) {
        int id = i * 128 + t;
        int r = id >> 3, c8 = id & 7;
        int b = r >> 4, h = r & 15;
        *(uint4*)((char*)Qs + r * 128 + ((c8 ^ (r & 7)) << 4)) =
            *(const uint4*)(g_Qh + (size_t)(b * NQ + q) * DM + h * DH + c8 * 8);
    }
    __syncthreads();

    float acc[2][4][4];
#pragma unroll
    for (int i = 0; i < 2; i++)
#pragma unroll
        for (int j = 0; j < 4; j++)
#pragma unroll
            for (int k = 0; k < 4; k++) acc[i][j][k] = 0.0f;

#pragma unroll
    for (int ks = 0; ks < 4; ks++) {
        int c0 = ks * 2;
        uint32_t bf[2][4];
#pragma unroll
        for (int j = 0; j < 2; j++) {
            int rowb = w * 32 + j * 16 + (lane & 15);
            int ch = c0 + (lane >> 4);
            ldsm4(bf[j], sRp + (uint32_t)(rowb * 128 + ((ch ^ (rowb & 7)) << 4)));
        }
#pragma unroll
        for (int mi = 0; mi < 2; mi++) {
            int rowa = mi * 16 + (lane & 15);
            int ch = c0 + (lane >> 4);
            uint32_t af[4];
            ldsm4(af, sQs + (uint32_t)(rowa * 128 + ((ch ^ (rowa & 7)) << 4)));
#pragma unroll
            for (int ni = 0; ni < 4; ni++) {
                int j = ni >> 1, s = ni & 1;
                mma16816(acc[mi][ni], af, bf[j][s], bf[j][s + 2]);
            }
        }
    }

#pragma unroll
    for (int mi = 0; mi < 2; mi++) {
#pragma unroll
        for (int ni = 0; ni < 4; ni++) {
            int m = mi * 16 + (lane >> 2);           // bh
            int n = k0 + w * 32 + ni * 8 + (lane & 3) * 2;
            float* p0 = attn + ((size_t)m * NQ + q) * NKV + n;
            float* p1 = attn + ((size_t)(m + 8) * NQ + q) * NKV + n;
            float2 c0v = *(float2*)p0, c1v = *(float2*)p1;
            c0v.x += SCALE * acc[mi][ni][0]; c0v.y += SCALE * acc[mi][ni][1];
            c1v.x += SCALE * acc[mi][ni][2]; c1v.y += SCALE * acc[mi][ni][3];
            *(float2*)p0 = c0v;
            *(float2*)p1 = c1v;
        }
    }
}

// ---------------- softmax (in place, warp-shuffle reductions) ----------------
__global__ void softmax_kernel(float* __restrict__ attn) {
    __shared__ float wm[8], ws[8];
    size_t row = blockIdx.x;
    float4* p = (float4*)(attn + row * (size_t)NKV);
    int t = threadIdx.x, lane = t & 31, w = t >> 5;
    float4 v1 = p[t], v2 = p[t + 256];
    float m = fmaxf(fmaxf(fmaxf(v1.x, v1.y), fmaxf(v1.z, v1.w)),
                    fmaxf(fmaxf(v2.x, v2.y), fmaxf(v2.z, v2.w)));
#pragma unroll
    for (int o = 16; o > 0; o >>= 1) m = fmaxf(m, __shfl_xor_sync(0xffffffffu, m, o));
    if (lane == 0) wm[w] = m;
    __syncthreads();
    float M = fmaxf(fmaxf(fmaxf(wm[0], wm[1]), fmaxf(wm[2], wm[3])),
                    fmaxf(fmaxf(wm[4], wm[5]), fmaxf(wm[6], wm[7])));
    v1.x = __expf(v1.x - M); v1.y = __expf(v1.y - M); v1.z = __expf(v1.z - M); v1.w = __expf(v1.w - M);
    v2.x = __expf(v2.x - M); v2.y = __expf(v2.y - M); v2.z = __expf(v2.z - M); v2.w = __expf(v2.w - M);
    float s = v1.x + v1.y + v1.z + v1.w + v2.x + v2.y + v2.z + v2.w;
#pragma unroll
    for (int o = 16; o > 0; o >>= 1) s += __shfl_xor_sync(0xffffffffu, s, o);
    if (lane == 0) ws[w] = s;
    __syncthreads();
    float inv = 1.0f / (ws[0] + ws[1] + ws[2] + ws[3] + ws[4] + ws[5] + ws[6] + ws[7]);
    v1.x *= inv; v1.y *= inv; v1.z *= inv; v1.w *= inv;
    v2.x *= inv; v2.y *= inv; v2.z *= inv; v2.w *= inv;
    p[t] = v1;
    p[t + 256] = v2;
}

// == av HMMA, double-buffered: B via cp.async; A via register prefetch + split ==
#define AV_ST 49152
#define AV_AH 0
#define AV_AL 16384
#define AV_BH 32768
#define AV_BL 40960
#define AV_TOTAL 98304

__global__ __launch_bounds__(256, 2) void av_mma(const float* __restrict__ attn) {
    extern __shared__ char smem[];
    uint32_t sb = smem_u32(smem);
    int t = threadIdx.x, lane = t & 31, wid = t >> 5;
    int wm = wid >> 1, wn = wid & 1;
    int bhead = blockIdx.y;
    int b = bhead >> 4, h = bhead & 15;
    int q0 = blockIdx.x * 128;

    float acc[2][4][4];
#pragma unroll
    for (int i = 0; i < 2; i++)
#pragma unroll
        for (int j = 0; j < 4; j++)
#pragma unroll
            for (int k = 0; k < 4; k++) acc[i][j][k] = 0.0f;

    float4 rA[8];
    auto ldA = [&](int kt) {
#pragma unroll
        for (int i = 0; i < 8; i++) {
            int idx = i * 256 + t;
            int r = idx >> 4, c4 = idx & 15;
            rA[i] = *(const float4*)(attn + ((size_t)bhead * NQ + q0 + r) * NKV + kt * 64 + c4 * 4);
        }
    };
    auto stsA = [&](int st) {
        char* base = smem + st * AV_ST;
#pragma unroll
        for (int i = 0; i < 8; i++) {
            int idx = i * 256 + t;
            int r = idx >> 4, c4 = idx & 15;
            __nv_bfloat16 hh[4], ll[4];
            split_bf16(rA[i].x, hh[0], ll[0]); split_bf16(rA[i].y, hh[1], ll[1]);
            split_bf16(rA[i].z, hh[2], ll[2]); split_bf16(rA[i].w, hh[3], ll[3]);
            int c8 = c4 >> 1, half = c4 & 1;
            uint32_t off = (uint32_t)(r * 128 + ((c8 ^ (r & 7)) << 4) + half * 8);
            *(uint2*)(base + AV_AH + off) = *(uint2*)hh;
            *(uint2*)(base + AV_AL + off) = *(uint2*)ll;
        }
    };
    auto issueB = [&](int kt) {
        uint32_t base = sb + (uint32_t)(kt & 1) * AV_ST;
#pragma unroll
        for (int i = 0; i < 2; i++) {
            int id2 = i * 256 + t;
            int r = id2 >> 3, c8 = id2 & 7;
            uint32_t off = (uint32_t)(r * 128 + ((c8 ^ (r & 7)) << 4));
            size_t gv = ((size_t)bhead * DH + r) * NKV + kt * 64 + c8 * 8;
            CP_A16(base + AV_BH + off, g_Vth + gv);
            CP_A16(base + AV_BL + off, g_Vtl + gv);
        }
    };

    // prologue
    issueB(0); CP_COMMIT();
    ldA(0); stsA(0);
    issueB(1); CP_COMMIT();
    ldA(1);
    CP_WAIT1();
    __syncthreads();

    for (int kt = 0; kt < 32; kt++) {
        uint32_t base = sb + (uint32_t)(kt & 1) * AV_ST;
#pragma unroll
        for (int ks = 0; ks < 4; ks++) {
            int c0 = ks * 2;
            uint32_t bh2[2][4], bl2[2][4];
#pragma unroll
            for (int j = 0; j < 2; j++) {
                int rowb = wn * 32 + j * 16 + (lane & 15);
                int ch = c0 + (lane >> 4);
                uint32_t so = (uint32_t)(rowb * 128 + ((ch ^ (rowb & 7)) << 4));
                ldsm4(bh2[j], base + AV_BH + so);
                ldsm4(bl2[j], base + AV_BL + so);
            }
#pragma unroll
            for (int mi = 0; mi < 2; mi++) {
                int rowa = wm * 32 + mi * 16 + (lane & 15);
                int ch = c0 + (lane >> 4);
                uint32_t so = (uint32_t)(rowa * 128 + ((ch ^ (rowa & 7)) << 4));
                uint32_t ah[4], al[4];
                ldsm4(ah, base + AV_AH + so);
                ldsm4(al, base + AV_AL + so);
#pragma unroll
                for (int ni = 0; ni < 4; ni++) {
                    int j = ni >> 1, s = ni & 1;
                    mma16816(acc[mi][ni], ah, bh2[j][s], bh2[j][s + 2]);
                    mma16816(acc[mi][ni], ah, bl2[j][s], bl2[j][s + 2]);
                    mma16816(acc[mi][ni], al, bh2[j][s], bh2[j][s + 2]);
                }
            }
        }
        if (kt + 1 < 32) {
            stsA((kt + 1) & 1);   // rA holds chunk kt+1
            if (kt + 2 < 32) { issueB(kt + 2); CP_COMMIT(); ldA(kt + 2); CP_WAIT1(); }
            else CP_WAIT0();
            __syncthreads();
        }
    }

#pragma unroll
    for (int mi = 0; mi < 2; mi++) {
#pragma unroll
        for (int ni = 0; ni < 4; ni++) {
            int m = q0 + wm * 32 + mi * 16 + (lane >> 2);
            int n = wn * 32 + ni * 8 + (lane & 3) * 2;
            __nv_bfloat16 h0, l0, h1, l1;
            split_bf16(acc[mi][ni][0], h0, l0); split_bf16(acc[mi][ni][1], h1, l1);
            *(__nv_bfloat162*)(g_ctxh + (size_t)(b * NQ + m) * DM + h * DH + n) = __nv_bfloat162(h0, h1);
            *(__nv_bfloat162*)(g_ctxl + (size_t)(b * NQ + m) * DM + h * DH + n) = __nv_bfloat162(l0, l1);
            split_bf16(acc[mi][ni][2], h0, l0); split_bf16(acc[mi][ni][3], h1, l1);
            *(__nv_bfloat162*)(g_ctxh + (size_t)(b * NQ + m + 8) * DM + h * DH + n) = __nv_bfloat162(h0, h1);
            *(__nv_bfloat162*)(g_ctxl + (size_t)(b * NQ + m + 8) * DM + h * DH + n) = __nv_bfloat162(l0, l1);
        }
    }
}

// ---------------- launch ----------------
extern "C" void kernel_launch(void* const* d_in, const int* in_sizes, int n_in,
                              void* d_out, int out_size) {
    const float* q = (const float*)d_in[0];
    const float* kv = (const float*)d_in[1];
    const unsigned char* mask = (const unsigned char*)d_in[2];
    const float* rpe = (const float*)d_in[3];
    const float* Wq = (const float*)d_in[4];
    const float* bq = (const float*)d_in[5];
    const float* Wk = (const float*)d_in[6];
    const float* bk = (const float*)d_in[7];
    const float* Wv = (const float*)d_in[8];
    const float* bv = (const float*)d_in[9];
    const float* Wo = (const float*)d_in[10];
    const float* bo = (const float*)d_in[11];
    const float* lg = (const float*)d_in[12];
    const float* lb = (const float*)d_in[13];

    float* out = (float*)d_out;
    const size_t ATT = (size_t)BB * NH * NQ * NKV;
    const size_t OUTN = (size_t)BB * NQ * DM;
    float* attn;
    if ((size_t)out_size >= ATT + OUTN) {
        attn = out + ((size_t)out_size - ATT);
    } else {
        void* p;
        cudaGetSymbolAddress(&p, g_attn_fallback);
        attn = (float*)p;
    }

#define SYMF(sym) ([]{ void* p; cudaGetSymbolAddress(&p, sym); return (float*)p; }())
#define SYMB(sym) ([]{ void* p; cudaGetSymbolAddress(&p, sym); return (__nv_bfloat16*)p; }())
    float* p_V = SYMF(g_V);
    __nv_bfloat16* p_qnh = SYMB(g_qnh);   __nv_bfloat16* p_qnl = SYMB(g_qnl);
    __nv_bfloat16* p_kvnh = SYMB(g_kvnh); __nv_bfloat16* p_kvnl = SYMB(g_kvnl);
    __nv_bfloat16* p_Wqh = SYMB(g_Wqh);   __nv_bfloat16* p_Wql = SYMB(g_Wql);
    __nv_bfloat16* p_Wkh = SYMB(g_Wkh);   __nv_bfloat16* p_Wkl = SYMB(g_Wkl);
    __nv_bfloat16* p_Wvh = SYMB(g_Wvh);   __nv_bfloat16* p_Wvl = SYMB(g_Wvl);
    __nv_bfloat16* p_Woh = SYMB(g_Woh);   __nv_bfloat16* p_Wol = SYMB(g_Wol);
    __nv_bfloat16* p_ctxh = SYMB(g_ctxh); __nv_bfloat16* p_ctxl = SYMB(g_ctxl);
    __nv_bfloat16* p_Qh = SYMB(g_Qh);     __nv_bfloat16* p_Ql = SYMB(g_Ql);
    __nv_bfloat16* p_Kh = SYMB(g_Kh);     __nv_bfloat16* p_Kl = SYMB(g_Kl);

    cudaFuncSetAttribute(gemm_mma, cudaFuncAttributeMaxDynamicSharedMemorySize, GS_TOTAL);
    cudaFuncSetAttribute(qk_mma, cudaFuncAttributeMaxDynamicSharedMemorySize, 65536);
    cudaFuncSetAttribute(av_mma, cudaFuncAttributeMaxDynamicSharedMemorySize, AV_TOTAL);

    // side stream for the V pipeline + Wo conversion (off the qk/rpe/softmax critical path)
    cudaStream_t s2;
    cudaStreamCreate(&s2);
    cudaEvent_t evFork, evJoin;
    cudaEventCreateWithFlags(&evFork, cudaEventDisableTiming);
    cudaEventCreateWithFlags(&evJoin, cudaEventDisableTiming);

    dim3 wt(32, 8);
    dim3 wg(32, 32);

    // main chain
    mask_kernel<<<1, 256>>>(mask);
    ln_kernel<<<BB * NQ + BB * NKV, 256>>>(q, kv, lg, lb);
    cudaEventRecord(evFork, 0);

    wconv_kernel<<<wg, wt>>>(Wq, p_Wqh, p_Wql);
    wconv_kernel<<<wg, wt>>>(Wk, p_Wkh, p_Wkl);
    gemm_mma<<<dim3(8, 16), 256, GS_TOTAL>>>(p_qnh, p_qnl, p_Wqh, p_Wql, bq, nullptr, p_Qh, p_Ql);
    gemm_mma<<<dim3(8, 32), 256, GS_TOTAL>>>(p_kvnh, p_kvnl, p_Wkh, p_Wkl, bk, nullptr, p_Kh, p_Kl);
    qk_mma<<<dim3(NKV / 128, NQ / 128, BB * NH), 256, 65536>>>(attn);
    rpe_mma<<<dim3(NKV / 128, NQ), 128>>>(rpe, attn);
    softmax_kernel<<<BB * NH * NQ, 256>>>(attn);

    // side chain: V projection + transpose/split + Wo conversion
    cudaStreamWaitEvent(s2, evFork, 0);
    wconv_kernel<<<wg, wt, 0, s2>>>(Wv, p_Wvh, p_Wvl);
    gemm_mma<<<dim3(8, 32), 256, GS_TOTAL, s2>>>(p_kvnh, p_kvnl, p_Wvh, p_Wvl, bv, p_V, nullptr, nullptr);
    vconv_kernel<<<dim3(NKV / 32, 2, BB * NH), wt, 0, s2>>>();
    wconv_kernel<<<wg, wt, 0, s2>>>(Wo, p_Woh, p_Wol);
    cudaEventRecord(evJoin, s2);

    // join: av needs softmax (main) + vconv (s2); final gemm needs Wo conv (s2)
    cudaStreamWaitEvent(0, evJoin, 0);
    av_mma<<<dim3(NQ / 128, BB * NH), 256, AV_TOTAL>>>(attn);
    gemm_mma<<<dim3(8, 16), 256, GS_TOTAL>>>(p_ctxh, p_ctxl, p_Woh, p_Wol, bo, out, nullptr, nullptr);
}